// round 1
// baseline (speedup 1.0000x reference)
#include <cuda_runtime.h>
#include <math.h>

#define FULL 0xffffffffu

constexpr int Nn = 100000;
constexpr int Ee = 1600000;
constexpr int Gg = 1000;
constexpr int Ss = 32;       // state dim
constexpr int Hh = 128;      // hidden dim
constexpr int ROUNDS = 5;
constexpr float NEG_SLOPE = 0.01f;
constexpr float LN_EPS = 1e-5f;

// Scratch (no allocation allowed): double-buffered node state + graph accumulator
__device__ float g_state[2][Nn * Ss];   // 2 x 12.8 MB
__device__ float g_gs[Gg * Ss];         // 128 KB

__device__ __forceinline__ float lrelu(float v) {
    return v >= 0.f ? v : NEG_SLOPE * v;
}

// ---------------------------------------------------------------------------
// zero state buffer 0 and graph accumulator
__global__ void zero_kernel() {
    int i = blockIdx.x * blockDim.x + threadIdx.x;
    int stride = gridDim.x * blockDim.x;
    for (int k = i; k < Nn * Ss; k += stride) g_state[0][k] = 0.f;
    for (int k = i; k < Gg * Ss; k += stride) g_gs[k] = 0.f;
}

// copy state[src] -> state[dst] (float4)
__global__ void copy_kernel(int dst, int src) {
    int i = blockIdx.x * blockDim.x + threadIdx.x;
    const float4* s = reinterpret_cast<const float4*>(g_state[src]);
    float4* d = reinterpret_cast<float4*>(g_state[dst]);
    int n4 = Nn * Ss / 4;
    for (int k = i; k < n4; k += gridDim.x * blockDim.x) d[k] = s[k];
}

// ---------------------------------------------------------------------------
// Edge MLP + scatter. Warp processes 4 edges per iteration.
// Layer1: lane computes h[4*lane .. 4*lane+3] for each of 4 edges.
// Layer2: lane (e = lane>>3, jb = lane&7) computes msg[4*jb .. 4*jb+3] of edge e.
__global__ void __launch_bounds__(192) edge_kernel(
    int inb,
    const int* __restrict__ nf, const int* __restrict__ nt,
    const float* __restrict__ ec,
    const float* __restrict__ W1, const float* __restrict__ b1,
    const float* __restrict__ g1, const float* __restrict__ be1,
    const float* __restrict__ W2, const float* __restrict__ b2,
    const float* __restrict__ g2, const float* __restrict__ be2)
{
    __shared__ float sW1[33 * 128];     // 16896 B
    __shared__ float sW2[128 * 32];     // 16384 B
    __shared__ float sb1[128], sg1[128], sbe1[128];
    __shared__ float sb2[32], sg2[32], sbe2[32];
    __shared__ float sh[6][4][132];     // h staging, padded rows (bank-conflict-free)

    const float* __restrict__ state_in = g_state[inb];
    float* __restrict__ state_out = g_state[inb ^ 1];

    int tid = threadIdx.x;
    for (int i = tid; i < 33 * 128; i += 192) sW1[i] = W1[i];
    for (int i = tid; i < 128 * 32; i += 192) sW2[i] = W2[i];
    if (tid < 128) { sb1[tid] = b1[tid]; sg1[tid] = g1[tid]; sbe1[tid] = be1[tid]; }
    if (tid < 32)  { sb2[tid] = b2[tid]; sg2[tid] = g2[tid]; sbe2[tid] = be2[tid]; }
    __syncthreads();

    int lane = tid & 31;
    int w = tid >> 5;
    int warp_global = blockIdx.x * 6 + w;
    int nwarps = gridDim.x * 6;
    int ngroups = Ee / 4;

    // per-lane layer2 assignment
    int le = lane >> 3;       // which of the 4 edges
    int jb = lane & 7;        // output block: j = 4*jb .. 4*jb+3
    const float* hrow = &sh[w][0][0] + le * 132;

    float4 b1v = *(const float4*)&sb1[4 * lane];
    float4 g1v = *(const float4*)&sg1[4 * lane];
    float4 be1v = *(const float4*)&sbe1[4 * lane];
    float4 b2v = *(const float4*)&sb2[4 * jb];
    float4 g2v = *(const float4*)&sg2[4 * jb];
    float4 be2v = *(const float4*)&sbe2[4 * jb];

    for (int g = warp_global; g < ngroups; g += nwarps) {
        int ebase = g * 4;
        float x[4], c[4];
        int dst[4];
#pragma unroll
        for (int e = 0; e < 4; e++) {
            int src = nf[ebase + e];
            x[e] = state_in[src * Ss + lane];
            c[e] = ec[ebase + e];
            dst[e] = nt[ebase + e];
        }

        // ------------- layer 1: (33 -> 128) -------------
        float4 acc0 = b1v, acc1 = b1v, acc2 = b1v, acc3 = b1v;
#pragma unroll
        for (int i = 0; i < 32; i++) {
            float4 wv = *(const float4*)&sW1[i * 128 + 4 * lane];
            float x0 = __shfl_sync(FULL, x[0], i);
            float x1 = __shfl_sync(FULL, x[1], i);
            float x2 = __shfl_sync(FULL, x[2], i);
            float x3 = __shfl_sync(FULL, x[3], i);
            acc0.x += x0 * wv.x; acc0.y += x0 * wv.y; acc0.z += x0 * wv.z; acc0.w += x0 * wv.w;
            acc1.x += x1 * wv.x; acc1.y += x1 * wv.y; acc1.z += x1 * wv.z; acc1.w += x1 * wv.w;
            acc2.x += x2 * wv.x; acc2.y += x2 * wv.y; acc2.z += x2 * wv.z; acc2.w += x2 * wv.w;
            acc3.x += x3 * wv.x; acc3.y += x3 * wv.y; acc3.z += x3 * wv.z; acc3.w += x3 * wv.w;
        }
        {   // coulomb row (row 32 of W1)
            float4 wv = *(const float4*)&sW1[32 * 128 + 4 * lane];
            acc0.x += c[0] * wv.x; acc0.y += c[0] * wv.y; acc0.z += c[0] * wv.z; acc0.w += c[0] * wv.w;
            acc1.x += c[1] * wv.x; acc1.y += c[1] * wv.y; acc1.z += c[1] * wv.z; acc1.w += c[1] * wv.w;
            acc2.x += c[2] * wv.x; acc2.y += c[2] * wv.y; acc2.z += c[2] * wv.z; acc2.w += c[2] * wv.w;
            acc3.x += c[3] * wv.x; acc3.y += c[3] * wv.y; acc3.z += c[3] * wv.z; acc3.w += c[3] * wv.w;
        }

        // LN + lrelu per edge, stage h into shared
#pragma unroll
        for (int e = 0; e < 4; e++) {
            float4 a = (e == 0) ? acc0 : (e == 1) ? acc1 : (e == 2) ? acc2 : acc3;
            float s = a.x + a.y + a.z + a.w;
            float s2 = a.x * a.x + a.y * a.y + a.z * a.z + a.w * a.w;
#pragma unroll
            for (int o = 16; o; o >>= 1) {
                s += __shfl_xor_sync(FULL, s, o);
                s2 += __shfl_xor_sync(FULL, s2, o);
            }
            float mean = s * (1.f / 128.f);
            float var = s2 * (1.f / 128.f) - mean * mean;
            float rstd = rsqrtf(var + LN_EPS);
            float4 hv;
            hv.x = lrelu((a.x - mean) * rstd * g1v.x + be1v.x);
            hv.y = lrelu((a.y - mean) * rstd * g1v.y + be1v.y);
            hv.z = lrelu((a.z - mean) * rstd * g1v.z + be1v.z);
            hv.w = lrelu((a.w - mean) * rstd * g1v.w + be1v.w);
            *(float4*)&sh[w][e][4 * lane] = hv;
        }
        __syncwarp();

        // ------------- layer 2: (128 -> 32) -------------
        float4 m = b2v;
#pragma unroll 8
        for (int i4 = 0; i4 < 32; i4++) {
            float4 hv = *(const float4*)&hrow[4 * i4];
            float4 w0 = *(const float4*)&sW2[(4 * i4 + 0) * 32 + 4 * jb];
            float4 w1 = *(const float4*)&sW2[(4 * i4 + 1) * 32 + 4 * jb];
            float4 w2 = *(const float4*)&sW2[(4 * i4 + 2) * 32 + 4 * jb];
            float4 w3 = *(const float4*)&sW2[(4 * i4 + 3) * 32 + 4 * jb];
            m.x += hv.x * w0.x + hv.y * w1.x + hv.z * w2.x + hv.w * w3.x;
            m.y += hv.x * w0.y + hv.y * w1.y + hv.z * w2.y + hv.w * w3.y;
            m.z += hv.x * w0.z + hv.y * w1.z + hv.z * w2.z + hv.w * w3.z;
            m.w += hv.x * w0.w + hv.y * w1.w + hv.z * w2.w + hv.w * w3.w;
        }

        // LN over the 32 outputs of edge le (distributed across 8 lanes)
        float s = m.x + m.y + m.z + m.w;
        float s2 = m.x * m.x + m.y * m.y + m.z * m.z + m.w * m.w;
#pragma unroll
        for (int o = 4; o; o >>= 1) {
            s += __shfl_xor_sync(FULL, s, o);
            s2 += __shfl_xor_sync(FULL, s2, o);
        }
        float mean = s * (1.f / 32.f);
        float var = s2 * (1.f / 32.f) - mean * mean;
        float rstd = rsqrtf(var + LN_EPS);
        float4 msg;
        msg.x = lrelu((m.x - mean) * rstd * g2v.x + be2v.x);
        msg.y = lrelu((m.y - mean) * rstd * g2v.y + be2v.y);
        msg.z = lrelu((m.z - mean) * rstd * g2v.z + be2v.z);
        msg.w = lrelu((m.w - mean) * rstd * g2v.w + be2v.w);

        // scatter-add (one 16B atomic per lane)
        int dd = (le < 2) ? (le == 0 ? dst[0] : dst[1]) : (le == 2 ? dst[2] : dst[3]);
        atomicAdd(reinterpret_cast<float4*>(&state_out[dd * Ss + 4 * jb]), msg);
        __syncwarp();
    }
}

// ---------------------------------------------------------------------------
// segment-sum node states into graph states (float4 atomics)
__global__ void graphsum_kernel(int inb, const int* __restrict__ ngi) {
    int t = blockIdx.x * blockDim.x + threadIdx.x;
    int total = Nn * (Ss / 4);
    if (t >= total) return;
    int n = t >> 3;          // node
    int q = t & 7;           // which float4 of the 32-dim row
    const float4* s = reinterpret_cast<const float4*>(g_state[inb]);
    float4 v = s[t];
    int g = ngi[n];
    atomicAdd(reinterpret_cast<float4*>(&g_gs[g * Ss + 4 * q]), v);
}

// ---------------------------------------------------------------------------
// readout: warp per graph. (32 -> 128) + LN + lrelu, then (128 -> 2), softplus
__global__ void __launch_bounds__(128) readout_kernel(
    const float* __restrict__ Wo1, const float* __restrict__ bo1,
    const float* __restrict__ go, const float* __restrict__ beo,
    const float* __restrict__ Wo2, const float* __restrict__ bo2,
    float* __restrict__ out)
{
    __shared__ float sW[32 * 128];
    __shared__ float sb[128], sg[128], sbe[128];
    __shared__ float sW2[256];
    __shared__ float sb2[2];

    int tid = threadIdx.x;
    for (int i = tid; i < 32 * 128; i += 128) sW[i] = Wo1[i];
    sb[tid] = bo1[tid]; sg[tid] = go[tid]; sbe[tid] = beo[tid];
    if (tid < 256 - 128) sW2[tid + 128] = Wo2[tid + 128];
    sW2[tid] = Wo2[tid];
    if (tid < 2) sb2[tid] = bo2[tid];
    __syncthreads();

    int lane = tid & 31;
    int w = tid >> 5;
    int g = blockIdx.x * 4 + w;
    if (g >= Gg) return;

    float x = g_gs[g * Ss + lane];
    float4 a;
    a.x = sb[4 * lane]; a.y = sb[4 * lane + 1]; a.z = sb[4 * lane + 2]; a.w = sb[4 * lane + 3];
#pragma unroll
    for (int i = 0; i < 32; i++) {
        float xi = __shfl_sync(FULL, x, i);
        float4 wv = *(const float4*)&sW[i * 128 + 4 * lane];
        a.x += xi * wv.x; a.y += xi * wv.y; a.z += xi * wv.z; a.w += xi * wv.w;
    }
    float s = a.x + a.y + a.z + a.w;
    float s2 = a.x * a.x + a.y * a.y + a.z * a.z + a.w * a.w;
#pragma unroll
    for (int o = 16; o; o >>= 1) {
        s += __shfl_xor_sync(FULL, s, o);
        s2 += __shfl_xor_sync(FULL, s2, o);
    }
    float mean = s * (1.f / 128.f);
    float var = s2 * (1.f / 128.f) - mean * mean;
    float rstd = rsqrtf(var + LN_EPS);
    float h0 = lrelu((a.x - mean) * rstd * sg[4 * lane + 0] + sbe[4 * lane + 0]);
    float h1 = lrelu((a.y - mean) * rstd * sg[4 * lane + 1] + sbe[4 * lane + 1]);
    float h2 = lrelu((a.z - mean) * rstd * sg[4 * lane + 2] + sbe[4 * lane + 2]);
    float h3 = lrelu((a.w - mean) * rstd * sg[4 * lane + 3] + sbe[4 * lane + 3]);

    float p0 = h0 * sW2[(4 * lane + 0) * 2] + h1 * sW2[(4 * lane + 1) * 2]
             + h2 * sW2[(4 * lane + 2) * 2] + h3 * sW2[(4 * lane + 3) * 2];
    float p1 = h0 * sW2[(4 * lane + 0) * 2 + 1] + h1 * sW2[(4 * lane + 1) * 2 + 1]
             + h2 * sW2[(4 * lane + 2) * 2 + 1] + h3 * sW2[(4 * lane + 3) * 2 + 1];
#pragma unroll
    for (int o = 16; o; o >>= 1) {
        p0 += __shfl_xor_sync(FULL, p0, o);
        p1 += __shfl_xor_sync(FULL, p1, o);
    }
    if (lane == 0) {
        float mu = p0 + sb2[0];
        float v = p1 + sb2[1];
        float sp = (v > 0.f) ? v + log1pf(expf(-v)) : log1pf(expf(v));
        out[g * 2 + 0] = mu;
        out[g * 2 + 1] = sp;
    }
}

// ---------------------------------------------------------------------------
extern "C" void kernel_launch(void* const* d_in, const int* in_sizes, int n_in,
                              void* d_out, int out_size) {
    const int* nf = (const int*)d_in[0];
    const int* nt = (const int*)d_in[1];
    const float* ec = (const float*)d_in[2];
    const int* ngi = (const int*)d_in[3];
    // d_in[4], d_in[5]: num_nodes / num_graphs scalars (compile-time constants here)
    const float* W1 = (const float*)d_in[6];
    const float* b1 = (const float*)d_in[7];
    const float* g1 = (const float*)d_in[8];
    const float* be1 = (const float*)d_in[9];
    const float* W2 = (const float*)d_in[10];
    const float* b2 = (const float*)d_in[11];
    const float* g2 = (const float*)d_in[12];
    const float* be2 = (const float*)d_in[13];
    const float* Wo1 = (const float*)d_in[14];
    const float* bo1 = (const float*)d_in[15];
    const float* go = (const float*)d_in[16];
    const float* beo = (const float*)d_in[17];
    const float* Wo2 = (const float*)d_in[18];
    const float* bo2 = (const float*)d_in[19];
    float* out = (float*)d_out;

    zero_kernel<<<4096, 256>>>();

    int cur = 0;
    for (int r = 0; r < ROUNDS; r++) {
        copy_kernel<<<3125, 256>>>(cur ^ 1, cur);
        edge_kernel<<<2048, 192>>>(cur, nf, nt, ec,
                                   W1, b1, g1, be1, W2, b2, g2, be2);
        cur ^= 1;
    }

    graphsum_kernel<<<(Nn * 8 + 255) / 256, 256>>>(cur, ngi);
    readout_kernel<<<(Gg + 3) / 4, 128>>>(Wo1, bo1, go, beo, Wo2, bo2, out);
}

// round 2
// speedup vs baseline: 1.3666x; 1.3666x over previous
#include <cuda_runtime.h>
#include <math.h>

#define FULL 0xffffffffu
typedef unsigned long long u64;

constexpr int Nn = 100000;
constexpr int Ee = 1600000;
constexpr int Gg = 1000;
constexpr int Ss = 32;       // state dim
constexpr int Hh = 128;      // hidden dim
constexpr int ROUNDS = 5;
constexpr float NEG_SLOPE = 0.01f;
constexpr float LN_EPS = 1e-5f;

// Scratch: double-buffered node state, hoisted layer-1 output, graph accumulator
__device__ float g_state[2][Nn * Ss];   // 2 x 12.8 MB
__device__ float g_y[Nn * Hh];          // 51.2 MB (y = state @ W1[:32] + b1)
__device__ float g_gs[Gg * Ss];         // 128 KB

__device__ __forceinline__ float lrelu(float v) {
    return v >= 0.f ? v : NEG_SLOPE * v;
}

// ---- packed f32x2 helpers (ptxas never auto-generates FFMA2) ----
__device__ __forceinline__ u64 pack2(float lo, float hi) {
    u64 r; asm("mov.b64 %0,{%1,%2};" : "=l"(r) : "f"(lo), "f"(hi)); return r;
}
__device__ __forceinline__ void unpack2(u64 v, float& lo, float& hi) {
    asm("mov.b64 {%0,%1},%2;" : "=f"(lo), "=f"(hi) : "l"(v));
}
__device__ __forceinline__ u64 fma2(u64 a, u64 b, u64 c) {
    u64 d; asm("fma.rn.f32x2 %0,%1,%2,%3;" : "=l"(d) : "l"(a), "l"(b), "l"(c)); return d;
}
__device__ __forceinline__ u64 add2(u64 a, u64 b) {
    u64 d; asm("add.rn.f32x2 %0,%1,%2;" : "=l"(d) : "l"(a), "l"(b)); return d;
}
__device__ __forceinline__ u64 mul2(u64 a, u64 b) {
    u64 d; asm("mul.rn.f32x2 %0,%1,%2;" : "=l"(d) : "l"(a), "l"(b)); return d;
}

// ---------------------------------------------------------------------------
__global__ void zero_kernel() {
    int i = blockIdx.x * blockDim.x + threadIdx.x;
    int stride = gridDim.x * blockDim.x;
    for (int k = i; k < Nn * Ss; k += stride) g_state[0][k] = 0.f;
    for (int k = i; k < Gg * Ss; k += stride) g_gs[k] = 0.f;
}

__global__ void copy_kernel(int dst, int src) {
    int i = blockIdx.x * blockDim.x + threadIdx.x;
    const float4* s = reinterpret_cast<const float4*>(g_state[src]);
    float4* d = reinterpret_cast<float4*>(g_state[dst]);
    int n4 = Nn * Ss / 4;
    for (int k = i; k < n4; k += gridDim.x * blockDim.x) d[k] = s[k];
}

// ---------------------------------------------------------------------------
// Node-level hoisted layer-1 GEMM: y[n] = state[n] @ W1[:32] + b1
// Warp processes 4 nodes; lane computes 4 hidden outputs per node.
__global__ void __launch_bounds__(192) node_gemm_kernel(
    int inb, const float* __restrict__ W1, const float* __restrict__ b1)
{
    __shared__ float sW1[32 * 128];
    __shared__ float sb1[128];
    const float* __restrict__ state_in = g_state[inb];

    int tid = threadIdx.x;
    for (int i = tid; i < 32 * 128; i += 192) sW1[i] = W1[i];
    if (tid < 128) sb1[tid] = b1[tid];
    __syncthreads();

    int lane = tid & 31;
    int w = tid >> 5;
    int warp_global = blockIdx.x * 6 + w;
    int nwarps = gridDim.x * 6;
    int ngroups = Nn / 4;

    float4 b1v = *(const float4*)&sb1[4 * lane];

    for (int g = warp_global; g < ngroups; g += nwarps) {
        int nbase = g * 4;
        float x0 = state_in[(nbase + 0) * Ss + lane];
        float x1 = state_in[(nbase + 1) * Ss + lane];
        float x2 = state_in[(nbase + 2) * Ss + lane];
        float x3 = state_in[(nbase + 3) * Ss + lane];

        float4 a0 = b1v, a1 = b1v, a2 = b1v, a3 = b1v;
#pragma unroll
        for (int i = 0; i < 32; i++) {
            float4 wv = *(const float4*)&sW1[i * 128 + 4 * lane];
            float s0 = __shfl_sync(FULL, x0, i);
            float s1 = __shfl_sync(FULL, x1, i);
            float s2 = __shfl_sync(FULL, x2, i);
            float s3 = __shfl_sync(FULL, x3, i);
            a0.x += s0 * wv.x; a0.y += s0 * wv.y; a0.z += s0 * wv.z; a0.w += s0 * wv.w;
            a1.x += s1 * wv.x; a1.y += s1 * wv.y; a1.z += s1 * wv.z; a1.w += s1 * wv.w;
            a2.x += s2 * wv.x; a2.y += s2 * wv.y; a2.z += s2 * wv.z; a2.w += s2 * wv.w;
            a3.x += s3 * wv.x; a3.y += s3 * wv.y; a3.z += s3 * wv.z; a3.w += s3 * wv.w;
        }
        *(float4*)&g_y[(nbase + 0) * Hh + 4 * lane] = a0;
        *(float4*)&g_y[(nbase + 1) * Hh + 4 * lane] = a1;
        *(float4*)&g_y[(nbase + 2) * Hh + 4 * lane] = a2;
        *(float4*)&g_y[(nbase + 3) * Hh + 4 * lane] = a3;
    }
}

// ---------------------------------------------------------------------------
// Edge kernel: per 4-edge group:
//   hpre_e = y[from_e] + c_e * W1row32         (gather + elementwise)
//   h_e    = lrelu(LN(hpre_e))
//   msg_e  = lrelu(LN(h_e @ W2 + b2))          (f32x2 packed over edge pairs)
//   state_out[to_e] += msg_e                    (float4 atomics)
__global__ void __launch_bounds__(192) edge_kernel(
    int inb,
    const int* __restrict__ nf, const int* __restrict__ nt,
    const float* __restrict__ ec,
    const float* __restrict__ W1,
    const float* __restrict__ g1, const float* __restrict__ be1,
    const float* __restrict__ W2, const float* __restrict__ b2,
    const float* __restrict__ g2, const float* __restrict__ be2)
{
    // W2 duplicated pairs: for K-pair t, lane j reads float4 (w[2t][j], w[2t][j], w[2t+1][j], w[2t+1][j])
    __shared__ float4 sW2q[64 * 32];        // 32 KB
    __shared__ u64 sh01[6][Hh];             // 6 KB  (h pairs, edges 0/1)
    __shared__ u64 sh23[6][Hh];             // 6 KB  (h pairs, edges 2/3)
    __shared__ float smsg[6][4][32];        // 3 KB

    float* __restrict__ state_out = g_state[inb ^ 1];

    int tid = threadIdx.x;
    for (int p = tid; p < 64 * 32; p += 192) {
        int t = p >> 5, jj = p & 31;
        float a = W2[(2 * t) * 32 + jj];
        float b = W2[(2 * t + 1) * 32 + jj];
        sW2q[p] = make_float4(a, a, b, b);
    }
    __syncthreads();

    int lane = tid & 31;
    int w = tid >> 5;
    int warp_global = blockIdx.x * 6 + w;
    int nwarps = gridDim.x * 6;
    int ngroups = Ee / 4;

    // per-lane constants (registers, no smem needed)
    float4 w32v = *(const float4*)&W1[32 * 128 + 4 * lane];  // coulomb row
    float4 g1v = *(const float4*)&g1[4 * lane];
    float4 be1v = *(const float4*)&be1[4 * lane];
    float b2j = b2[lane], g2j = g2[lane], be2j = be2[lane];
    u64 bias2 = pack2(b2j, b2j);

    u64* sh01w = sh01[w];
    u64* sh23w = sh23[w];
    const float4* yv = (const float4*)g_y;

    for (int g = warp_global; g < ngroups; g += nwarps) {
        int ebase = g * 4;
        int4 NF = *(const int4*)&nf[ebase];
        int4 NT = *(const int4*)&nt[ebase];
        float4 C = *(const float4*)&ec[ebase];

        // gather + elementwise layer-1 epilogue + LN + lrelu, per edge
        float4 h[4];
        int srcs[4] = {NF.x, NF.y, NF.z, NF.w};
        float cs[4] = {C.x, C.y, C.z, C.w};
#pragma unroll
        for (int e = 0; e < 4; e++) {
            float4 a = yv[srcs[e] * (Hh / 4) + lane];
            float c = cs[e];
            a.x = fmaf(c, w32v.x, a.x);
            a.y = fmaf(c, w32v.y, a.y);
            a.z = fmaf(c, w32v.z, a.z);
            a.w = fmaf(c, w32v.w, a.w);
            float s = a.x + a.y + a.z + a.w;
            float q = a.x * a.x + a.y * a.y + a.z * a.z + a.w * a.w;
#pragma unroll
            for (int o = 16; o; o >>= 1) {
                s += __shfl_xor_sync(FULL, s, o);
                q += __shfl_xor_sync(FULL, q, o);
            }
            float mean = s * (1.f / 128.f);
            float var = q * (1.f / 128.f) - mean * mean;
            float rstd = rsqrtf(var + LN_EPS);
            float4 tv, hv;
            tv.x = rstd * g1v.x; tv.y = rstd * g1v.y; tv.z = rstd * g1v.z; tv.w = rstd * g1v.w;
            hv.x = lrelu(fmaf(a.x - mean, tv.x, be1v.x));
            hv.y = lrelu(fmaf(a.y - mean, tv.y, be1v.y));
            hv.z = lrelu(fmaf(a.z - mean, tv.z, be1v.z));
            hv.w = lrelu(fmaf(a.w - mean, tv.w, be1v.w));
            h[e] = hv;
        }

        // stage h as edge-pairs (f32x2) into shared
        {
            ulonglong2 v;
            v.x = pack2(h[0].x, h[1].x); v.y = pack2(h[0].y, h[1].y);
            *(ulonglong2*)&sh01w[4 * lane] = v;
            v.x = pack2(h[0].z, h[1].z); v.y = pack2(h[0].w, h[1].w);
            *(ulonglong2*)&sh01w[4 * lane + 2] = v;
            v.x = pack2(h[2].x, h[3].x); v.y = pack2(h[2].y, h[3].y);
            *(ulonglong2*)&sh23w[4 * lane] = v;
            v.x = pack2(h[2].z, h[3].z); v.y = pack2(h[2].w, h[3].w);
            *(ulonglong2*)&sh23w[4 * lane + 2] = v;
        }
        __syncwarp();

        // layer 2: lane j computes msg[j] for all 4 edges (2 f32x2 accumulators)
        u64 m01 = bias2, m23 = bias2;
        const ulonglong2* H01 = (const ulonglong2*)sh01w;
        const ulonglong2* H23 = (const ulonglong2*)sh23w;
        const ulonglong2* W2q = (const ulonglong2*)sW2q;
#pragma unroll 8
        for (int t = 0; t < 64; t++) {
            ulonglong2 A = H01[t];
            ulonglong2 B = H23[t];
            ulonglong2 Wv = W2q[t * 32 + lane];
            m01 = fma2(A.x, Wv.x, m01);
            m01 = fma2(A.y, Wv.y, m01);
            m23 = fma2(B.x, Wv.x, m23);
            m23 = fma2(B.y, Wv.y, m23);
        }

        // LN over 32 outputs (across lanes), packed reductions
        u64 s01 = m01, q01 = mul2(m01, m01);
        u64 s23 = m23, q23 = mul2(m23, m23);
#pragma unroll
        for (int o = 16; o; o >>= 1) {
            s01 = add2(s01, __shfl_xor_sync(FULL, s01, o));
            q01 = add2(q01, __shfl_xor_sync(FULL, q01, o));
            s23 = add2(s23, __shfl_xor_sync(FULL, s23, o));
            q23 = add2(q23, __shfl_xor_sync(FULL, q23, o));
        }
        float S[4], Q[4], M[4];
        unpack2(s01, S[0], S[1]); unpack2(s23, S[2], S[3]);
        unpack2(q01, Q[0], Q[1]); unpack2(q23, Q[2], Q[3]);
        unpack2(m01, M[0], M[1]); unpack2(m23, M[2], M[3]);
#pragma unroll
        for (int e = 0; e < 4; e++) {
            float mean = S[e] * (1.f / 32.f);
            float var = Q[e] * (1.f / 32.f) - mean * mean;
            float rstd = rsqrtf(var + LN_EPS);
            float msg = lrelu(fmaf((M[e] - mean) * rstd, g2j, be2j));
            smsg[w][e][lane] = msg;
        }
        __syncwarp();

        // scatter: lane handles (edge le, output block jb) -> one float4 atomic
        int le = lane >> 3;
        int jb = lane & 7;
        float4 mv = *(const float4*)&smsg[w][le][4 * jb];
        int dd = (le == 0) ? NT.x : (le == 1) ? NT.y : (le == 2) ? NT.z : NT.w;
        atomicAdd(reinterpret_cast<float4*>(&state_out[dd * Ss + 4 * jb]), mv);
        __syncwarp();
    }
}

// ---------------------------------------------------------------------------
__global__ void graphsum_kernel(int inb, const int* __restrict__ ngi) {
    int t = blockIdx.x * blockDim.x + threadIdx.x;
    int total = Nn * (Ss / 4);
    if (t >= total) return;
    int n = t >> 3;
    int q = t & 7;
    const float4* s = reinterpret_cast<const float4*>(g_state[inb]);
    float4 v = s[t];
    int g = ngi[n];
    atomicAdd(reinterpret_cast<float4*>(&g_gs[g * Ss + 4 * q]), v);
}

// ---------------------------------------------------------------------------
__global__ void __launch_bounds__(128) readout_kernel(
    const float* __restrict__ Wo1, const float* __restrict__ bo1,
    const float* __restrict__ go, const float* __restrict__ beo,
    const float* __restrict__ Wo2, const float* __restrict__ bo2,
    float* __restrict__ out)
{
    __shared__ float sW[32 * 128];
    __shared__ float sb[128], sg[128], sbe[128];
    __shared__ float sW2[256];
    __shared__ float sb2[2];

    int tid = threadIdx.x;
    for (int i = tid; i < 32 * 128; i += 128) sW[i] = Wo1[i];
    sb[tid] = bo1[tid]; sg[tid] = go[tid]; sbe[tid] = beo[tid];
    sW2[tid] = Wo2[tid];
    sW2[tid + 128] = Wo2[tid + 128];
    if (tid < 2) sb2[tid] = bo2[tid];
    __syncthreads();

    int lane = tid & 31;
    int w = tid >> 5;
    int g = blockIdx.x * 4 + w;
    if (g >= Gg) return;

    float x = g_gs[g * Ss + lane];
    float4 a;
    a.x = sb[4 * lane]; a.y = sb[4 * lane + 1]; a.z = sb[4 * lane + 2]; a.w = sb[4 * lane + 3];
#pragma unroll
    for (int i = 0; i < 32; i++) {
        float xi = __shfl_sync(FULL, x, i);
        float4 wv = *(const float4*)&sW[i * 128 + 4 * lane];
        a.x += xi * wv.x; a.y += xi * wv.y; a.z += xi * wv.z; a.w += xi * wv.w;
    }
    float s = a.x + a.y + a.z + a.w;
    float s2 = a.x * a.x + a.y * a.y + a.z * a.z + a.w * a.w;
#pragma unroll
    for (int o = 16; o; o >>= 1) {
        s += __shfl_xor_sync(FULL, s, o);
        s2 += __shfl_xor_sync(FULL, s2, o);
    }
    float mean = s * (1.f / 128.f);
    float var = s2 * (1.f / 128.f) - mean * mean;
    float rstd = rsqrtf(var + LN_EPS);
    float h0 = lrelu((a.x - mean) * rstd * sg[4 * lane + 0] + sbe[4 * lane + 0]);
    float h1 = lrelu((a.y - mean) * rstd * sg[4 * lane + 1] + sbe[4 * lane + 1]);
    float h2 = lrelu((a.z - mean) * rstd * sg[4 * lane + 2] + sbe[4 * lane + 2]);
    float h3 = lrelu((a.w - mean) * rstd * sg[4 * lane + 3] + sbe[4 * lane + 3]);

    float p0 = h0 * sW2[(4 * lane + 0) * 2] + h1 * sW2[(4 * lane + 1) * 2]
             + h2 * sW2[(4 * lane + 2) * 2] + h3 * sW2[(4 * lane + 3) * 2];
    float p1 = h0 * sW2[(4 * lane + 0) * 2 + 1] + h1 * sW2[(4 * lane + 1) * 2 + 1]
             + h2 * sW2[(4 * lane + 2) * 2 + 1] + h3 * sW2[(4 * lane + 3) * 2 + 1];
#pragma unroll
    for (int o = 16; o; o >>= 1) {
        p0 += __shfl_xor_sync(FULL, p0, o);
        p1 += __shfl_xor_sync(FULL, p1, o);
    }
    if (lane == 0) {
        float mu = p0 + sb2[0];
        float v = p1 + sb2[1];
        float sp = (v > 0.f) ? v + log1pf(expf(-v)) : log1pf(expf(v));
        out[g * 2 + 0] = mu;
        out[g * 2 + 1] = sp;
    }
}

// ---------------------------------------------------------------------------
extern "C" void kernel_launch(void* const* d_in, const int* in_sizes, int n_in,
                              void* d_out, int out_size) {
    const int* nf = (const int*)d_in[0];
    const int* nt = (const int*)d_in[1];
    const float* ec = (const float*)d_in[2];
    const int* ngi = (const int*)d_in[3];
    const float* W1 = (const float*)d_in[6];
    const float* b1 = (const float*)d_in[7];
    const float* g1 = (const float*)d_in[8];
    const float* be1 = (const float*)d_in[9];
    const float* W2 = (const float*)d_in[10];
    const float* b2 = (const float*)d_in[11];
    const float* g2 = (const float*)d_in[12];
    const float* be2 = (const float*)d_in[13];
    const float* Wo1 = (const float*)d_in[14];
    const float* bo1 = (const float*)d_in[15];
    const float* go = (const float*)d_in[16];
    const float* beo = (const float*)d_in[17];
    const float* Wo2 = (const float*)d_in[18];
    const float* bo2 = (const float*)d_in[19];
    float* out = (float*)d_out;

    zero_kernel<<<4096, 256>>>();

    int cur = 0;
    for (int r = 0; r < ROUNDS; r++) {
        copy_kernel<<<3125, 256>>>(cur ^ 1, cur);
        node_gemm_kernel<<<1024, 192>>>(cur, W1, b1);
        edge_kernel<<<2048, 192>>>(cur, nf, nt, ec,
                                   W1, g1, be1, W2, b2, g2, be2);
        cur ^= 1;
    }

    graphsum_kernel<<<(Nn * 8 + 255) / 256, 256>>>(cur, ngi);
    readout_kernel<<<(Gg + 3) / 4, 128>>>(Wo1, bo1, go, beo, Wo2, bo2, out);
}

// round 5
// speedup vs baseline: 3.9703x; 2.9052x over previous
#include <cuda_runtime.h>
#include <cuda_bf16.h>
#include <math.h>
#include <stdint.h>

#define FULL 0xffffffffu
typedef unsigned long long u64;

constexpr int Nn = 100000;
constexpr int Ee = 1600000;
constexpr int Gg = 1000;
constexpr int Ss = 32;
constexpr int Hh = 128;
constexpr int ROUNDS = 5;
constexpr float NEG_SLOPE = 0.01f;
constexpr float LN_EPS = 1e-5f;

// smem layout for edge_kernel (all bf16 matrices, row pitch 272B = 17*16, conflict-free)
constexpr int APITCH = 272;
constexpr int AWARP = 16 * APITCH;                 // 4352 B per 16x128 bf16 matrix
constexpr int OFF_B_H = 8 * 2 * AWARP;             // 69632 (after 8 warps x {Ah,Al})
constexpr int OFF_B_L = OFF_B_H + 32 * APITCH;     // 78336
constexpr int EDGE_DSMEM = OFF_B_L + 32 * APITCH;  // 87040
constexpr int EDGE_GRID = 296;                     // 2 blocks/SM persistent

__device__ float g_state[2][Nn * Ss];
__device__ float g_y[Nn * Hh];
__device__ float g_gs[Gg * Ss];

__device__ __forceinline__ float lrelu(float v) { return v >= 0.f ? v : NEG_SLOPE * v; }

__device__ __forceinline__ uint32_t smem_u32(const void* p) {
    uint32_t a;
    asm("{ .reg .u64 t; cvta.to.shared.u64 t, %1; cvt.u32.u64 %0, t; }" : "=r"(a) : "l"(p));
    return a;
}

__device__ __forceinline__ void ldsm4(uint32_t r[4], uint32_t addr) {
    asm volatile("ldmatrix.sync.aligned.m8n8.x4.shared.b16 {%0,%1,%2,%3}, [%4];"
                 : "=r"(r[0]), "=r"(r[1]), "=r"(r[2]), "=r"(r[3]) : "r"(addr));
}

__device__ __forceinline__ void mma16816(float acc[4], const uint32_t a[4],
                                         uint32_t b0, uint32_t b1) {
    asm volatile(
        "mma.sync.aligned.m16n8k16.row.col.f32.bf16.bf16.f32 "
        "{%0,%1,%2,%3}, {%4,%5,%6,%7}, {%8,%9}, {%0,%1,%2,%3};"
        : "+f"(acc[0]), "+f"(acc[1]), "+f"(acc[2]), "+f"(acc[3])
        : "r"(a[0]), "r"(a[1]), "r"(a[2]), "r"(a[3]), "r"(b0), "r"(b1));
}

// ---------------------------------------------------------------------------
__global__ void zero_kernel() {
    int i = blockIdx.x * blockDim.x + threadIdx.x;
    int stride = gridDim.x * blockDim.x;
    for (int k = i; k < Nn * Ss; k += stride) g_state[0][k] = 0.f;
    for (int k = i; k < Gg * Ss; k += stride) g_gs[k] = 0.f;
}

__global__ void copy_kernel(int dst, int src) {
    int i = blockIdx.x * blockDim.x + threadIdx.x;
    const float4* s = reinterpret_cast<const float4*>(g_state[src]);
    float4* d = reinterpret_cast<float4*>(g_state[dst]);
    int n4 = Nn * Ss / 4;
    for (int k = i; k < n4; k += gridDim.x * blockDim.x) d[k] = s[k];
}

// ---------------------------------------------------------------------------
// y[n] = state[n] @ W1[:32] + b1   (hoisted layer-1 GEMM, fp32 SIMT)
__global__ void __launch_bounds__(192) node_gemm_kernel(
    int inb, const float* __restrict__ W1, const float* __restrict__ b1)
{
    __shared__ float sW1[32 * 128];
    __shared__ float sb1[128];
    const float* __restrict__ state_in = g_state[inb];

    int tid = threadIdx.x;
    for (int i = tid; i < 32 * 128; i += 192) sW1[i] = W1[i];
    if (tid < 128) sb1[tid] = b1[tid];
    __syncthreads();

    int lane = tid & 31;
    int w = tid >> 5;
    int warp_global = blockIdx.x * 6 + w;
    int nwarps = gridDim.x * 6;
    int ngroups = Nn / 4;

    float4 b1v = *(const float4*)&sb1[4 * lane];

    for (int g = warp_global; g < ngroups; g += nwarps) {
        int nbase = g * 4;
        float x0 = state_in[(nbase + 0) * Ss + lane];
        float x1 = state_in[(nbase + 1) * Ss + lane];
        float x2 = state_in[(nbase + 2) * Ss + lane];
        float x3 = state_in[(nbase + 3) * Ss + lane];

        float4 a0 = b1v, a1 = b1v, a2 = b1v, a3 = b1v;
#pragma unroll
        for (int i = 0; i < 32; i++) {
            float4 wv = *(const float4*)&sW1[i * 128 + 4 * lane];
            float s0 = __shfl_sync(FULL, x0, i);
            float s1 = __shfl_sync(FULL, x1, i);
            float s2 = __shfl_sync(FULL, x2, i);
            float s3 = __shfl_sync(FULL, x3, i);
            a0.x += s0 * wv.x; a0.y += s0 * wv.y; a0.z += s0 * wv.z; a0.w += s0 * wv.w;
            a1.x += s1 * wv.x; a1.y += s1 * wv.y; a1.z += s1 * wv.z; a1.w += s1 * wv.w;
            a2.x += s2 * wv.x; a2.y += s2 * wv.y; a2.z += s2 * wv.z; a2.w += s2 * wv.w;
            a3.x += s3 * wv.x; a3.y += s3 * wv.y; a3.z += s3 * wv.z; a3.w += s3 * wv.w;
        }
        *(float4*)&g_y[(nbase + 0) * Hh + 4 * lane] = a0;
        *(float4*)&g_y[(nbase + 1) * Hh + 4 * lane] = a1;
        *(float4*)&g_y[(nbase + 2) * Hh + 4 * lane] = a2;
        *(float4*)&g_y[(nbase + 3) * Hh + 4 * lane] = a3;
    }
}

// ---------------------------------------------------------------------------
// Edge kernel: warp-independent 16-edge tiles.
//   h = lrelu(LN(y[from] + c*W1row32)) -> bf16 hi/lo -> private smem staging
//   D = Ah@Bh + Ah@Bl + Al@Bh via mma.sync m16n8k16 (fp32 accum)
//   msg = lrelu(LN(D + b2)); scatter float2 atomics.
__global__ void __launch_bounds__(256, 2) edge_kernel(
    int inb,
    const int* __restrict__ nf, const int* __restrict__ nt,
    const float* __restrict__ ec,
    const float* __restrict__ W1,
    const float* __restrict__ g1, const float* __restrict__ be1,
    const float* __restrict__ W2, const float* __restrict__ b2,
    const float* __restrict__ g2, const float* __restrict__ be2)
{
    extern __shared__ char dsm[];
    uint32_t sbase = smem_u32(dsm);

    int tid = threadIdx.x;
    int lane = tid & 31;
    int wid = tid >> 5;

    // Build B staging: sB[n][k] = W2[k][n], bf16 hi/lo, pitch APITCH
    for (int p = tid; p < 32 * 128; p += 256) {
        int n = p >> 7;
        int k = p & 127;
        float wv = W2[k * 32 + n];
        __nv_bfloat16 hb = __float2bfloat16(wv);
        __nv_bfloat16 lb = __float2bfloat16(wv - __bfloat162float(hb));
        *(__nv_bfloat16*)(dsm + OFF_B_H + n * APITCH + k * 2) = hb;
        *(__nv_bfloat16*)(dsm + OFF_B_L + n * APITCH + k * 2) = lb;
    }
    __syncthreads();

    // per-lane constants
    float4 w32v = *(const float4*)&W1[32 * 128 + 4 * lane];
    float4 g1v  = *(const float4*)&g1[4 * lane];
    float4 be1v = *(const float4*)&be1[4 * lane];

    int q = lane & 3;
    int rA = lane >> 2;          // row within warp-tile (0..7)
    int rB = rA + 8;

    float b2r[4][2], g2r[4][2], be2r[4][2];
#pragma unroll
    for (int t = 0; t < 4; t++) {
        int c = 8 * t + 2 * q;
        b2r[t][0] = b2[c];     b2r[t][1] = b2[c + 1];
        g2r[t][0] = g2[c];     g2r[t][1] = g2[c + 1];
        be2r[t][0] = be2[c];   be2r[t][1] = be2[c + 1];
    }

    // staging addresses
    char* aStoreH = dsm + wid * 2 * AWARP + lane * 8;
    char* aStoreL = aStoreH + AWARP;

    int aRow = lane & 15;
    int aColB = ((lane >> 4) & 1) * 16;
    uint32_t ldAH = sbase + wid * 2 * AWARP + aRow * APITCH + aColB;
    uint32_t ldAL = ldAH + AWARP;

    int bRow = ((lane >> 4) & 1) * 8 + (lane & 7);
    int bKB = ((lane >> 3) & 1) * 16;
    uint32_t ldBH01 = sbase + OFF_B_H + bRow * APITCH + bKB;
    uint32_t ldBH23 = ldBH01 + 16 * APITCH;
    uint32_t ldBL01 = sbase + OFF_B_L + bRow * APITCH + bKB;
    uint32_t ldBL23 = ldBL01 + 16 * APITCH;

    const float4* __restrict__ yv = (const float4*)g_y;
    float* __restrict__ state_out = g_state[inb ^ 1];

    int ngroups = Ee / 16;     // 100000
    int wg = blockIdx.x * 8 + wid;
    int nw = gridDim.x * 8;

    for (int g = wg; g < ngroups; g += nw) {
        int base = g * 16;

        // ---- gather + LN1 + bf16 split + stage (16 edge rows) ----
#pragma unroll 4
        for (int e = 0; e < 16; e++) {
            int src = __ldg(&nf[base + e]);
            float c = __ldg(&ec[base + e]);
            float4 a = yv[src * (Hh / 4) + lane];
            a.x = fmaf(c, w32v.x, a.x);
            a.y = fmaf(c, w32v.y, a.y);
            a.z = fmaf(c, w32v.z, a.z);
            a.w = fmaf(c, w32v.w, a.w);
            float s = a.x + a.y + a.z + a.w;
            float sq = a.x * a.x + a.y * a.y + a.z * a.z + a.w * a.w;
#pragma unroll
            for (int o = 16; o; o >>= 1) {
                s += __shfl_xor_sync(FULL, s, o);
                sq += __shfl_xor_sync(FULL, sq, o);
            }
            float mean = s * (1.f / 128.f);
            float var = sq * (1.f / 128.f) - mean * mean;
            float rstd = rsqrtf(var + LN_EPS);
            float4 hv;
            hv.x = lrelu(fmaf((a.x - mean) * rstd, g1v.x, be1v.x));
            hv.y = lrelu(fmaf((a.y - mean) * rstd, g1v.y, be1v.y));
            hv.z = lrelu(fmaf((a.z - mean) * rstd, g1v.z, be1v.z));
            hv.w = lrelu(fmaf((a.w - mean) * rstd, g1v.w, be1v.w));

            __nv_bfloat162 h01 = __float22bfloat162_rn(make_float2(hv.x, hv.y));
            __nv_bfloat162 h23 = __float22bfloat162_rn(make_float2(hv.z, hv.w));
            float2 f01 = __bfloat1622float2(h01);
            float2 f23 = __bfloat1622float2(h23);
            __nv_bfloat162 l01 = __float22bfloat162_rn(make_float2(hv.x - f01.x, hv.y - f01.y));
            __nv_bfloat162 l23 = __float22bfloat162_rn(make_float2(hv.z - f23.x, hv.w - f23.y));
            u64 packh = (u64)(*(uint32_t*)&h01) | ((u64)(*(uint32_t*)&h23) << 32);
            u64 packl = (u64)(*(uint32_t*)&l01) | ((u64)(*(uint32_t*)&l23) << 32);
            *(u64*)(aStoreH + e * APITCH) = packh;
            *(u64*)(aStoreL + e * APITCH) = packl;
        }
        __syncwarp();

        // ---- MMA: D = Ah@Bh + Ah@Bl + Al@Bh ----
        float acc[4][4];
#pragma unroll
        for (int t = 0; t < 4; t++)
#pragma unroll
            for (int j = 0; j < 4; j++) acc[t][j] = 0.f;

#pragma unroll
        for (int k = 0; k < 8; k++) {
            uint32_t ah[4], al[4], bh01[4], bh23[4], bl01[4], bl23[4];
            ldsm4(ah, ldAH + k * 32);
            ldsm4(al, ldAL + k * 32);
            ldsm4(bh01, ldBH01 + k * 32);
            ldsm4(bh23, ldBH23 + k * 32);
            ldsm4(bl01, ldBL01 + k * 32);
            ldsm4(bl23, ldBL23 + k * 32);

            mma16816(acc[0], ah, bh01[0], bh01[1]);
            mma16816(acc[1], ah, bh01[2], bh01[3]);
            mma16816(acc[2], ah, bh23[0], bh23[1]);
            mma16816(acc[3], ah, bh23[2], bh23[3]);

            mma16816(acc[0], ah, bl01[0], bl01[1]);
            mma16816(acc[1], ah, bl01[2], bl01[3]);
            mma16816(acc[2], ah, bl23[0], bl23[1]);
            mma16816(acc[3], ah, bl23[2], bl23[3]);

            mma16816(acc[0], al, bh01[0], bh01[1]);
            mma16816(acc[1], al, bh01[2], bh01[3]);
            mma16816(acc[2], al, bh23[0], bh23[1]);
            mma16816(acc[3], al, bh23[2], bh23[3]);
        }
        __syncwarp();

        // ---- epilogue: bias + LN2 (quad reduction) + scatter ----
        int dstA = __ldg(&nt[base + rA]);
        int dstB = __ldg(&nt[base + rB]);

        float mA[4][2], mB[4][2];
        float sA = 0.f, qA = 0.f, sB = 0.f, qB = 0.f;
#pragma unroll
        for (int t = 0; t < 4; t++) {
            mA[t][0] = acc[t][0] + b2r[t][0];
            mA[t][1] = acc[t][1] + b2r[t][1];
            mB[t][0] = acc[t][2] + b2r[t][0];
            mB[t][1] = acc[t][3] + b2r[t][1];
            sA += mA[t][0] + mA[t][1];
            qA += mA[t][0] * mA[t][0] + mA[t][1] * mA[t][1];
            sB += mB[t][0] + mB[t][1];
            qB += mB[t][0] * mB[t][0] + mB[t][1] * mB[t][1];
        }
#pragma unroll
        for (int o = 2; o; o >>= 1) {
            sA += __shfl_xor_sync(FULL, sA, o);
            qA += __shfl_xor_sync(FULL, qA, o);
            sB += __shfl_xor_sync(FULL, sB, o);
            qB += __shfl_xor_sync(FULL, qB, o);
        }
        float meanA = sA * (1.f / 32.f);
        float rstdA = rsqrtf(qA * (1.f / 32.f) - meanA * meanA + LN_EPS);
        float meanB = sB * (1.f / 32.f);
        float rstdB = rsqrtf(qB * (1.f / 32.f) - meanB * meanB + LN_EPS);

        float* rowA = &state_out[dstA * Ss];
        float* rowB = &state_out[dstB * Ss];
#pragma unroll
        for (int t = 0; t < 4; t++) {
            int c = 8 * t + 2 * q;
            float2 v;
            v.x = lrelu(fmaf((mA[t][0] - meanA) * rstdA, g2r[t][0], be2r[t][0]));
            v.y = lrelu(fmaf((mA[t][1] - meanA) * rstdA, g2r[t][1], be2r[t][1]));
            atomicAdd(reinterpret_cast<float2*>(&rowA[c]), v);
            float2 u;
            u.x = lrelu(fmaf((mB[t][0] - meanB) * rstdB, g2r[t][0], be2r[t][0]));
            u.y = lrelu(fmaf((mB[t][1] - meanB) * rstdB, g2r[t][1], be2r[t][1]));
            atomicAdd(reinterpret_cast<float2*>(&rowB[c]), u);
        }
    }
}

// ---------------------------------------------------------------------------
__global__ void graphsum_kernel(int inb, const int* __restrict__ ngi) {
    int t = blockIdx.x * blockDim.x + threadIdx.x;
    int total = Nn * (Ss / 4);
    if (t >= total) return;
    int n = t >> 3;
    int q = t & 7;
    const float4* s = reinterpret_cast<const float4*>(g_state[inb]);
    float4 v = s[t];
    int g = ngi[n];
    atomicAdd(reinterpret_cast<float4*>(&g_gs[g * Ss + 4 * q]), v);
}

// ---------------------------------------------------------------------------
__global__ void __launch_bounds__(128) readout_kernel(
    const float* __restrict__ Wo1, const float* __restrict__ bo1,
    const float* __restrict__ go, const float* __restrict__ beo,
    const float* __restrict__ Wo2, const float* __restrict__ bo2,
    float* __restrict__ out)
{
    __shared__ float sW[32 * 128];
    __shared__ float sb[128], sg[128], sbe[128];
    __shared__ float sW2[256];
    __shared__ float sb2[2];

    int tid = threadIdx.x;
    for (int i = tid; i < 32 * 128; i += 128) sW[i] = Wo1[i];
    sb[tid] = bo1[tid]; sg[tid] = go[tid]; sbe[tid] = beo[tid];
    sW2[tid] = Wo2[tid];
    sW2[tid + 128] = Wo2[tid + 128];
    if (tid < 2) sb2[tid] = bo2[tid];
    __syncthreads();

    int lane = tid & 31;
    int w = tid >> 5;
    int g = blockIdx.x * 4 + w;
    if (g >= Gg) return;

    float x = g_gs[g * Ss + lane];
    float4 a;
    a.x = sb[4 * lane]; a.y = sb[4 * lane + 1]; a.z = sb[4 * lane + 2]; a.w = sb[4 * lane + 3];
#pragma unroll
    for (int i = 0; i < 32; i++) {
        float xi = __shfl_sync(FULL, x, i);
        float4 wv = *(const float4*)&sW[i * 128 + 4 * lane];
        a.x += xi * wv.x; a.y += xi * wv.y; a.z += xi * wv.z; a.w += xi * wv.w;
    }
    float s = a.x + a.y + a.z + a.w;
    float s2 = a.x * a.x + a.y * a.y + a.z * a.z + a.w * a.w;
#pragma unroll
    for (int o = 16; o; o >>= 1) {
        s += __shfl_xor_sync(FULL, s, o);
        s2 += __shfl_xor_sync(FULL, s2, o);
    }
    float mean = s * (1.f / 128.f);
    float var = s2 * (1.f / 128.f) - mean * mean;
    float rstd = rsqrtf(var + LN_EPS);
    float h0 = lrelu((a.x - mean) * rstd * sg[4 * lane + 0] + sbe[4 * lane + 0]);
    float h1 = lrelu((a.y - mean) * rstd * sg[4 * lane + 1] + sbe[4 * lane + 1]);
    float h2 = lrelu((a.z - mean) * rstd * sg[4 * lane + 2] + sbe[4 * lane + 2]);
    float h3 = lrelu((a.w - mean) * rstd * sg[4 * lane + 3] + sbe[4 * lane + 3]);

    float p0 = h0 * sW2[(4 * lane + 0) * 2] + h1 * sW2[(4 * lane + 1) * 2]
             + h2 * sW2[(4 * lane + 2) * 2] + h3 * sW2[(4 * lane + 3) * 2];
    float p1 = h0 * sW2[(4 * lane + 0) * 2 + 1] + h1 * sW2[(4 * lane + 1) * 2 + 1]
             + h2 * sW2[(4 * lane + 2) * 2 + 1] + h3 * sW2[(4 * lane + 3) * 2 + 1];
#pragma unroll
    for (int o = 16; o; o >>= 1) {
        p0 += __shfl_xor_sync(FULL, p0, o);
        p1 += __shfl_xor_sync(FULL, p1, o);
    }
    if (lane == 0) {
        float mu = p0 + sb2[0];
        float v = p1 + sb2[1];
        float sp = (v > 0.f) ? v + log1pf(expf(-v)) : log1pf(expf(v));
        out[g * 2 + 0] = mu;
        out[g * 2 + 1] = sp;
    }
}

// ---------------------------------------------------------------------------
extern "C" void kernel_launch(void* const* d_in, const int* in_sizes, int n_in,
                              void* d_out, int out_size) {
    const int* nf = (const int*)d_in[0];
    const int* nt = (const int*)d_in[1];
    const float* ec = (const float*)d_in[2];
    const int* ngi = (const int*)d_in[3];
    const float* W1 = (const float*)d_in[6];
    const float* b1 = (const float*)d_in[7];
    const float* g1 = (const float*)d_in[8];
    const float* be1 = (const float*)d_in[9];
    const float* W2 = (const float*)d_in[10];
    const float* b2 = (const float*)d_in[11];
    const float* g2 = (const float*)d_in[12];
    const float* be2 = (const float*)d_in[13];
    const float* Wo1 = (const float*)d_in[14];
    const float* bo1 = (const float*)d_in[15];
    const float* go = (const float*)d_in[16];
    const float* beo = (const float*)d_in[17];
    const float* Wo2 = (const float*)d_in[18];
    const float* bo2 = (const float*)d_in[19];
    float* out = (float*)d_out;

    cudaFuncSetAttribute(edge_kernel, cudaFuncAttributeMaxDynamicSharedMemorySize, EDGE_DSMEM);

    zero_kernel<<<4096, 256>>>();

    int cur = 0;
    for (int r = 0; r < ROUNDS; r++) {
        copy_kernel<<<3125, 256>>>(cur ^ 1, cur);
        node_gemm_kernel<<<1024, 192>>>(cur, W1, b1);
        edge_kernel<<<EDGE_GRID, 256, EDGE_DSMEM>>>(cur, nf, nt, ec,
                                                    W1, g1, be1, W2, b2, g2, be2);
        cur ^= 1;
    }

    graphsum_kernel<<<(Nn * 8 + 255) / 256, 256>>>(cur, ngi);
    readout_kernel<<<(Gg + 3) / 4, 128>>>(Wo1, bo1, go, beo, Wo2, bo2, out);
}

// round 6
// speedup vs baseline: 4.9476x; 1.2461x over previous
#include <cuda_runtime.h>
#include <cuda_bf16.h>
#include <math.h>
#include <stdint.h>

#define FULL 0xffffffffu
typedef unsigned long long u64;

constexpr int Nn = 100000;
constexpr int Ee = 1600000;
constexpr int Gg = 1000;
constexpr int Ss = 32;
constexpr int Hh = 128;
constexpr int ROUNDS = 5;
constexpr float NEG_SLOPE = 0.01f;
constexpr float LN_EPS = 1e-5f;

// smem layout for edge_kernel (bf16 matrices, row pitch 272B, conflict-free ldmatrix)
constexpr int APITCH = 272;
constexpr int AWARP = 16 * APITCH;                 // 4352 B per 16x128 bf16 matrix
constexpr int OFF_B_H = 8 * 2 * AWARP;             // 69632
constexpr int OFF_B_L = OFF_B_H + 32 * APITCH;     // 78336
constexpr int EDGE_DSMEM = OFF_B_L + 32 * APITCH;  // 87040
constexpr int EDGE_GRID = 296;

__device__ float g_state[2][Nn * Ss];
__device__ float g_y[Nn * Hh];
__device__ float4 g_stats[Nn];          // (Sy, Qy, P, 0) per node
__device__ float g_gs[Gg * Ss];

__device__ __forceinline__ float lrelu(float v) { return v >= 0.f ? v : NEG_SLOPE * v; }

__device__ __forceinline__ uint32_t smem_u32(const void* p) {
    uint32_t a;
    asm("{ .reg .u64 t; cvta.to.shared.u64 t, %1; cvt.u32.u64 %0, t; }" : "=r"(a) : "l"(p));
    return a;
}

__device__ __forceinline__ void ldsm4(uint32_t r[4], uint32_t addr) {
    asm volatile("ldmatrix.sync.aligned.m8n8.x4.shared.b16 {%0,%1,%2,%3}, [%4];"
                 : "=r"(r[0]), "=r"(r[1]), "=r"(r[2]), "=r"(r[3]) : "r"(addr));
}

__device__ __forceinline__ void mma16816(float acc[4], const uint32_t a[4],
                                         uint32_t b0, uint32_t b1) {
    asm volatile(
        "mma.sync.aligned.m16n8k16.row.col.f32.bf16.bf16.f32 "
        "{%0,%1,%2,%3}, {%4,%5,%6,%7}, {%8,%9}, {%0,%1,%2,%3};"
        : "+f"(acc[0]), "+f"(acc[1]), "+f"(acc[2]), "+f"(acc[3])
        : "r"(a[0]), "r"(a[1]), "r"(a[2]), "r"(a[3]), "r"(b0), "r"(b1));
}

// ---------------------------------------------------------------------------
__global__ void zero_kernel() {
    int i = blockIdx.x * blockDim.x + threadIdx.x;
    int stride = gridDim.x * blockDim.x;
    for (int k = i; k < Nn * Ss; k += stride) g_state[0][k] = 0.f;
    for (int k = i; k < Gg * Ss; k += stride) g_gs[k] = 0.f;
}

// ---------------------------------------------------------------------------
// Per round: y[n] = state[n] @ W1[:32] + b1 ; stats (Sy,Qy,P) ; copy state->out
__global__ void __launch_bounds__(192) node_gemm_kernel(
    int inb, const float* __restrict__ W1, const float* __restrict__ b1)
{
    __shared__ float sW1[32 * 128];
    __shared__ float sb1[128];
    const float* __restrict__ state_in = g_state[inb];
    float* __restrict__ state_out = g_state[inb ^ 1];

    int tid = threadIdx.x;
    for (int i = tid; i < 32 * 128; i += 192) sW1[i] = W1[i];
    if (tid < 128) sb1[tid] = b1[tid];
    __syncthreads();

    int lane = tid & 31;
    int w = tid >> 5;
    int warp_global = blockIdx.x * 6 + w;
    int nwarps = gridDim.x * 6;
    int ngroups = Nn / 4;

    float4 b1v = *(const float4*)&sb1[4 * lane];
    float4 w32v = *(const float4*)&W1[32 * 128 + 4 * lane];

    for (int g = warp_global; g < ngroups; g += nwarps) {
        int nbase = g * 4;
        float x0 = state_in[(nbase + 0) * Ss + lane];
        float x1 = state_in[(nbase + 1) * Ss + lane];
        float x2 = state_in[(nbase + 2) * Ss + lane];
        float x3 = state_in[(nbase + 3) * Ss + lane];

        // fused copy (replaces copy_kernel)
        state_out[(nbase + 0) * Ss + lane] = x0;
        state_out[(nbase + 1) * Ss + lane] = x1;
        state_out[(nbase + 2) * Ss + lane] = x2;
        state_out[(nbase + 3) * Ss + lane] = x3;

        float4 a0 = b1v, a1 = b1v, a2 = b1v, a3 = b1v;
#pragma unroll
        for (int i = 0; i < 32; i++) {
            float4 wv = *(const float4*)&sW1[i * 128 + 4 * lane];
            float s0 = __shfl_sync(FULL, x0, i);
            float s1 = __shfl_sync(FULL, x1, i);
            float s2 = __shfl_sync(FULL, x2, i);
            float s3 = __shfl_sync(FULL, x3, i);
            a0.x += s0 * wv.x; a0.y += s0 * wv.y; a0.z += s0 * wv.z; a0.w += s0 * wv.w;
            a1.x += s1 * wv.x; a1.y += s1 * wv.y; a1.z += s1 * wv.z; a1.w += s1 * wv.w;
            a2.x += s2 * wv.x; a2.y += s2 * wv.y; a2.z += s2 * wv.z; a2.w += s2 * wv.w;
            a3.x += s3 * wv.x; a3.y += s3 * wv.y; a3.z += s3 * wv.z; a3.w += s3 * wv.w;
        }
        *(float4*)&g_y[(nbase + 0) * Hh + 4 * lane] = a0;
        *(float4*)&g_y[(nbase + 1) * Hh + 4 * lane] = a1;
        *(float4*)&g_y[(nbase + 2) * Hh + 4 * lane] = a2;
        *(float4*)&g_y[(nbase + 3) * Hh + 4 * lane] = a3;

        // per-node LN statistics: Sy, Qy, P = <y, w32>
#pragma unroll
        for (int e = 0; e < 4; e++) {
            float4 a = (e == 0) ? a0 : (e == 1) ? a1 : (e == 2) ? a2 : a3;
            float s = a.x + a.y + a.z + a.w;
            float q = a.x * a.x + a.y * a.y + a.z * a.z + a.w * a.w;
            float p = a.x * w32v.x + a.y * w32v.y + a.z * w32v.z + a.w * w32v.w;
#pragma unroll
            for (int o = 16; o; o >>= 1) {
                s += __shfl_xor_sync(FULL, s, o);
                q += __shfl_xor_sync(FULL, q, o);
                p += __shfl_xor_sync(FULL, p, o);
            }
            if (lane == 0) g_stats[nbase + e] = make_float4(s, q, p, 0.f);
        }
    }
}

// ---------------------------------------------------------------------------
// Edge kernel: warp-independent 16-edge tiles, LN1 via precomputed node stats.
__global__ void __launch_bounds__(256, 2) edge_kernel(
    int inb,
    const int* __restrict__ nf, const int* __restrict__ nt,
    const float* __restrict__ ec,
    const float* __restrict__ W1,
    const float* __restrict__ g1, const float* __restrict__ be1,
    const float* __restrict__ W2, const float* __restrict__ b2,
    const float* __restrict__ g2, const float* __restrict__ be2)
{
    extern __shared__ char dsm[];
    uint32_t sbase = smem_u32(dsm);

    int tid = threadIdx.x;
    int lane = tid & 31;
    int wid = tid >> 5;

    // Build B staging: sB[n][k] = W2[k][n], bf16 hi/lo
    for (int p = tid; p < 32 * 128; p += 256) {
        int n = p >> 7;
        int k = p & 127;
        float wv = W2[k * 32 + n];
        __nv_bfloat16 hb = __float2bfloat16(wv);
        __nv_bfloat16 lb = __float2bfloat16(wv - __bfloat162float(hb));
        *(__nv_bfloat16*)(dsm + OFF_B_H + n * APITCH + k * 2) = hb;
        *(__nv_bfloat16*)(dsm + OFF_B_L + n * APITCH + k * 2) = lb;
    }
    __syncthreads();

    // per-lane constants
    float4 w32v = *(const float4*)&W1[32 * 128 + 4 * lane];
    float4 g1v  = *(const float4*)&g1[4 * lane];
    float4 be1v = *(const float4*)&be1[4 * lane];

    // warp-wide scalars Sw = sum(w32), Qw = sum(w32^2)
    float Sw = w32v.x + w32v.y + w32v.z + w32v.w;
    float Qw = w32v.x * w32v.x + w32v.y * w32v.y + w32v.z * w32v.z + w32v.w * w32v.w;
#pragma unroll
    for (int o = 16; o; o >>= 1) {
        Sw += __shfl_xor_sync(FULL, Sw, o);
        Qw += __shfl_xor_sync(FULL, Qw, o);
    }

    int q = lane & 3;
    int rA = lane >> 2;
    int rB = rA + 8;

    float b2r[4][2], g2r[4][2], be2r[4][2];
#pragma unroll
    for (int t = 0; t < 4; t++) {
        int c = 8 * t + 2 * q;
        b2r[t][0] = b2[c];     b2r[t][1] = b2[c + 1];
        g2r[t][0] = g2[c];     g2r[t][1] = g2[c + 1];
        be2r[t][0] = be2[c];   be2r[t][1] = be2[c + 1];
    }

    char* aStoreH = dsm + wid * 2 * AWARP + lane * 8;
    char* aStoreL = aStoreH + AWARP;

    int aRow = lane & 15;
    int aColB = ((lane >> 4) & 1) * 16;
    uint32_t ldAH = sbase + wid * 2 * AWARP + aRow * APITCH + aColB;
    uint32_t ldAL = ldAH + AWARP;

    int bRow = ((lane >> 4) & 1) * 8 + (lane & 7);
    int bKB = ((lane >> 3) & 1) * 16;
    uint32_t ldBH01 = sbase + OFF_B_H + bRow * APITCH + bKB;
    uint32_t ldBH23 = ldBH01 + 16 * APITCH;
    uint32_t ldBL01 = sbase + OFF_B_L + bRow * APITCH + bKB;
    uint32_t ldBL23 = ldBL01 + 16 * APITCH;

    const float4* __restrict__ yv = (const float4*)g_y;
    float* __restrict__ state_out = g_state[inb ^ 1];

    int ngroups = Ee / 16;
    int wg = blockIdx.x * 8 + wid;
    int nw = gridDim.x * 8;

    for (int g = wg; g < ngroups; g += nw) {
        int base = g * 16;

        // ---- gather + stats-based LN1 + bf16 split + stage (16 rows) ----
#pragma unroll
        for (int j = 0; j < 4; j++) {
            int4 NF = *(const int4*)&nf[base + 4 * j];
            float4 C = *(const float4*)&ec[base + 4 * j];
            int srcs[4] = {NF.x, NF.y, NF.z, NF.w};
            float cs[4] = {C.x, C.y, C.z, C.w};
#pragma unroll
            for (int e = 0; e < 4; e++) {
                int src = srcs[e];
                float c = cs[e];
                float4 st = g_stats[src];                 // uniform per warp
                float4 a = yv[src * (Hh / 4) + lane];
                a.x = fmaf(c, w32v.x, a.x);
                a.y = fmaf(c, w32v.y, a.y);
                a.z = fmaf(c, w32v.z, a.z);
                a.w = fmaf(c, w32v.w, a.w);

                float s = fmaf(c, Sw, st.x);
                float qq = fmaf(c * c, Qw, fmaf(2.f * c, st.z, st.y));
                float mean = s * (1.f / 128.f);
                float var = qq * (1.f / 128.f) - mean * mean;
                float rstd = rsqrtf(var + LN_EPS);

                float4 hv;
                hv.x = lrelu(fmaf((a.x - mean) * rstd, g1v.x, be1v.x));
                hv.y = lrelu(fmaf((a.y - mean) * rstd, g1v.y, be1v.y));
                hv.z = lrelu(fmaf((a.z - mean) * rstd, g1v.z, be1v.z));
                hv.w = lrelu(fmaf((a.w - mean) * rstd, g1v.w, be1v.w));

                __nv_bfloat162 h01 = __float22bfloat162_rn(make_float2(hv.x, hv.y));
                __nv_bfloat162 h23 = __float22bfloat162_rn(make_float2(hv.z, hv.w));
                float2 f01 = __bfloat1622float2(h01);
                float2 f23 = __bfloat1622float2(h23);
                __nv_bfloat162 l01 = __float22bfloat162_rn(make_float2(hv.x - f01.x, hv.y - f01.y));
                __nv_bfloat162 l23 = __float22bfloat162_rn(make_float2(hv.z - f23.x, hv.w - f23.y));
                u64 packh = (u64)(*(uint32_t*)&h01) | ((u64)(*(uint32_t*)&h23) << 32);
                u64 packl = (u64)(*(uint32_t*)&l01) | ((u64)(*(uint32_t*)&l23) << 32);
                int row = 4 * j + e;
                *(u64*)(aStoreH + row * APITCH) = packh;
                *(u64*)(aStoreL + row * APITCH) = packl;
            }
        }
        __syncwarp();

        // ---- MMA: D = Ah@Bh + Ah@Bl + Al@Bh ----
        float acc[4][4];
#pragma unroll
        for (int t = 0; t < 4; t++)
#pragma unroll
            for (int j2 = 0; j2 < 4; j2++) acc[t][j2] = 0.f;

#pragma unroll
        for (int k = 0; k < 8; k++) {
            uint32_t ah[4], al[4], bh01[4], bh23[4], bl01[4], bl23[4];
            ldsm4(ah, ldAH + k * 32);
            ldsm4(al, ldAL + k * 32);
            ldsm4(bh01, ldBH01 + k * 32);
            ldsm4(bh23, ldBH23 + k * 32);
            ldsm4(bl01, ldBL01 + k * 32);
            ldsm4(bl23, ldBL23 + k * 32);

            mma16816(acc[0], ah, bh01[0], bh01[1]);
            mma16816(acc[1], ah, bh01[2], bh01[3]);
            mma16816(acc[2], ah, bh23[0], bh23[1]);
            mma16816(acc[3], ah, bh23[2], bh23[3]);

            mma16816(acc[0], ah, bl01[0], bl01[1]);
            mma16816(acc[1], ah, bl01[2], bl01[3]);
            mma16816(acc[2], ah, bl23[0], bl23[1]);
            mma16816(acc[3], ah, bl23[2], bl23[3]);

            mma16816(acc[0], al, bh01[0], bh01[1]);
            mma16816(acc[1], al, bh01[2], bh01[3]);
            mma16816(acc[2], al, bh23[0], bh23[1]);
            mma16816(acc[3], al, bh23[2], bh23[3]);
        }
        __syncwarp();

        // ---- epilogue: bias + LN2 (quad reduction) + scatter ----
        int dstA = __ldg(&nt[base + rA]);
        int dstB = __ldg(&nt[base + rB]);

        float mA[4][2], mB[4][2];
        float sA = 0.f, qA = 0.f, sB = 0.f, qB = 0.f;
#pragma unroll
        for (int t = 0; t < 4; t++) {
            mA[t][0] = acc[t][0] + b2r[t][0];
            mA[t][1] = acc[t][1] + b2r[t][1];
            mB[t][0] = acc[t][2] + b2r[t][0];
            mB[t][1] = acc[t][3] + b2r[t][1];
            sA += mA[t][0] + mA[t][1];
            qA += mA[t][0] * mA[t][0] + mA[t][1] * mA[t][1];
            sB += mB[t][0] + mB[t][1];
            qB += mB[t][0] * mB[t][0] + mB[t][1] * mB[t][1];
        }
#pragma unroll
        for (int o = 2; o; o >>= 1) {
            sA += __shfl_xor_sync(FULL, sA, o);
            qA += __shfl_xor_sync(FULL, qA, o);
            sB += __shfl_xor_sync(FULL, sB, o);
            qB += __shfl_xor_sync(FULL, qB, o);
        }
        float meanA = sA * (1.f / 32.f);
        float rstdA = rsqrtf(qA * (1.f / 32.f) - meanA * meanA + LN_EPS);
        float meanB = sB * (1.f / 32.f);
        float rstdB = rsqrtf(qB * (1.f / 32.f) - meanB * meanB + LN_EPS);

        float* rowA = &state_out[dstA * Ss];
        float* rowB = &state_out[dstB * Ss];
#pragma unroll
        for (int t = 0; t < 4; t++) {
            int c = 8 * t + 2 * q;
            float2 v;
            v.x = lrelu(fmaf((mA[t][0] - meanA) * rstdA, g2r[t][0], be2r[t][0]));
            v.y = lrelu(fmaf((mA[t][1] - meanA) * rstdA, g2r[t][1], be2r[t][1]));
            atomicAdd(reinterpret_cast<float2*>(&rowA[c]), v);
            float2 u;
            u.x = lrelu(fmaf((mB[t][0] - meanB) * rstdB, g2r[t][0], be2r[t][0]));
            u.y = lrelu(fmaf((mB[t][1] - meanB) * rstdB, g2r[t][1], be2r[t][1]));
            atomicAdd(reinterpret_cast<float2*>(&rowB[c]), u);
        }
    }
}

// ---------------------------------------------------------------------------
__global__ void graphsum_kernel(int inb, const int* __restrict__ ngi) {
    int t = blockIdx.x * blockDim.x + threadIdx.x;
    int total = Nn * (Ss / 4);
    if (t >= total) return;
    int n = t >> 3;
    int q = t & 7;
    const float4* s = reinterpret_cast<const float4*>(g_state[inb]);
    float4 v = s[t];
    int g = ngi[n];
    atomicAdd(reinterpret_cast<float4*>(&g_gs[g * Ss + 4 * q]), v);
}

// ---------------------------------------------------------------------------
__global__ void __launch_bounds__(128) readout_kernel(
    const float* __restrict__ Wo1, const float* __restrict__ bo1,
    const float* __restrict__ go, const float* __restrict__ beo,
    const float* __restrict__ Wo2, const float* __restrict__ bo2,
    float* __restrict__ out)
{
    __shared__ float sW[32 * 128];
    __shared__ float sb[128], sg[128], sbe[128];
    __shared__ float sW2[256];
    __shared__ float sb2[2];

    int tid = threadIdx.x;
    for (int i = tid; i < 32 * 128; i += 128) sW[i] = Wo1[i];
    sb[tid] = bo1[tid]; sg[tid] = go[tid]; sbe[tid] = beo[tid];
    sW2[tid] = Wo2[tid];
    sW2[tid + 128] = Wo2[tid + 128];
    if (tid < 2) sb2[tid] = bo2[tid];
    __syncthreads();

    int lane = tid & 31;
    int w = tid >> 5;
    int g = blockIdx.x * 4 + w;
    if (g >= Gg) return;

    float x = g_gs[g * Ss + lane];
    float4 a;
    a.x = sb[4 * lane]; a.y = sb[4 * lane + 1]; a.z = sb[4 * lane + 2]; a.w = sb[4 * lane + 3];
#pragma unroll
    for (int i = 0; i < 32; i++) {
        float xi = __shfl_sync(FULL, x, i);
        float4 wv = *(const float4*)&sW[i * 128 + 4 * lane];
        a.x += xi * wv.x; a.y += xi * wv.y; a.z += xi * wv.z; a.w += xi * wv.w;
    }
    float s = a.x + a.y + a.z + a.w;
    float s2 = a.x * a.x + a.y * a.y + a.z * a.z + a.w * a.w;
#pragma unroll
    for (int o = 16; o; o >>= 1) {
        s += __shfl_xor_sync(FULL, s, o);
        s2 += __shfl_xor_sync(FULL, s2, o);
    }
    float mean = s * (1.f / 128.f);
    float var = s2 * (1.f / 128.f) - mean * mean;
    float rstd = rsqrtf(var + LN_EPS);
    float h0 = lrelu((a.x - mean) * rstd * sg[4 * lane + 0] + sbe[4 * lane + 0]);
    float h1 = lrelu((a.y - mean) * rstd * sg[4 * lane + 1] + sbe[4 * lane + 1]);
    float h2 = lrelu((a.z - mean) * rstd * sg[4 * lane + 2] + sbe[4 * lane + 2]);
    float h3 = lrelu((a.w - mean) * rstd * sg[4 * lane + 3] + sbe[4 * lane + 3]);

    float p0 = h0 * sW2[(4 * lane + 0) * 2] + h1 * sW2[(4 * lane + 1) * 2]
             + h2 * sW2[(4 * lane + 2) * 2] + h3 * sW2[(4 * lane + 3) * 2];
    float p1 = h0 * sW2[(4 * lane + 0) * 2 + 1] + h1 * sW2[(4 * lane + 1) * 2 + 1]
             + h2 * sW2[(4 * lane + 2) * 2 + 1] + h3 * sW2[(4 * lane + 3) * 2 + 1];
#pragma unroll
    for (int o = 16; o; o >>= 1) {
        p0 += __shfl_xor_sync(FULL, p0, o);
        p1 += __shfl_xor_sync(FULL, p1, o);
    }
    if (lane == 0) {
        float mu = p0 + sb2[0];
        float v = p1 + sb2[1];
        float sp = (v > 0.f) ? v + log1pf(expf(-v)) : log1pf(expf(v));
        out[g * 2 + 0] = mu;
        out[g * 2 + 1] = sp;
    }
}

// ---------------------------------------------------------------------------
extern "C" void kernel_launch(void* const* d_in, const int* in_sizes, int n_in,
                              void* d_out, int out_size) {
    const int* nf = (const int*)d_in[0];
    const int* nt = (const int*)d_in[1];
    const float* ec = (const float*)d_in[2];
    const int* ngi = (const int*)d_in[3];
    const float* W1 = (const float*)d_in[6];
    const float* b1 = (const float*)d_in[7];
    const float* g1 = (const float*)d_in[8];
    const float* be1 = (const float*)d_in[9];
    const float* W2 = (const float*)d_in[10];
    const float* b2 = (const float*)d_in[11];
    const float* g2 = (const float*)d_in[12];
    const float* be2 = (const float*)d_in[13];
    const float* Wo1 = (const float*)d_in[14];
    const float* bo1 = (const float*)d_in[15];
    const float* go = (const float*)d_in[16];
    const float* beo = (const float*)d_in[17];
    const float* Wo2 = (const float*)d_in[18];
    const float* bo2 = (const float*)d_in[19];
    float* out = (float*)d_out;

    cudaFuncSetAttribute(edge_kernel, cudaFuncAttributeMaxDynamicSharedMemorySize, EDGE_DSMEM);

    zero_kernel<<<4096, 256>>>();

    int cur = 0;
    for (int r = 0; r < ROUNDS; r++) {
        node_gemm_kernel<<<1024, 192>>>(cur, W1, b1);   // also copies state cur -> cur^1
        edge_kernel<<<EDGE_GRID, 256, EDGE_DSMEM>>>(cur, nf, nt, ec,
                                                    W1, g1, be1, W2, b2, g2, be2);
        cur ^= 1;
    }

    graphsum_kernel<<<(Nn * 8 + 255) / 256, 256>>>(cur, ngi);
    readout_kernel<<<(Gg + 3) / 4, 128>>>(Wo1, bo1, go, beo, Wo2, bo2, out);
}

// round 7
// speedup vs baseline: 4.9630x; 1.0031x over previous
#include <cuda_runtime.h>
#include <cuda_bf16.h>
#include <math.h>
#include <stdint.h>

#define FULL 0xffffffffu
typedef unsigned long long u64;

constexpr int Nn = 100000;
constexpr int Ee = 1600000;
constexpr int Gg = 1000;
constexpr int Ss = 32;
constexpr int Hh = 128;
constexpr int ROUNDS = 5;
constexpr float NEG_SLOPE = 0.01f;
constexpr float LN_EPS = 1e-5f;

constexpr int APITCH = 272;
constexpr int AWARP = 16 * APITCH;
constexpr int OFF_B_H = 8 * 2 * AWARP;             // 69632
constexpr int OFF_B_L = OFF_B_H + 32 * APITCH;     // 78336
constexpr int EDGE_DSMEM = OFF_B_L + 32 * APITCH;  // 87040
constexpr int EDGE_GRID = 296;

__device__ float g_state[2][Nn * Ss];
__device__ float g_y[Nn * Hh];
__device__ float4 g_stats[Nn];
__device__ float g_gs[Gg * Ss];

__device__ __forceinline__ float lrelu(float v) { return v >= 0.f ? v : NEG_SLOPE * v; }

// ---- packed f32x2 helpers ----
__device__ __forceinline__ u64 pack2(float lo, float hi) {
    u64 r; asm("mov.b64 %0,{%1,%2};" : "=l"(r) : "f"(lo), "f"(hi)); return r;
}
__device__ __forceinline__ void unpack2(u64 v, float& lo, float& hi) {
    asm("mov.b64 {%0,%1},%2;" : "=f"(lo), "=f"(hi) : "l"(v));
}
__device__ __forceinline__ u64 fma2(u64 a, u64 b, u64 c) {
    u64 d; asm("fma.rn.f32x2 %0,%1,%2,%3;" : "=l"(d) : "l"(a), "l"(b), "l"(c)); return d;
}
__device__ __forceinline__ u64 add2(u64 a, u64 b) {
    u64 d; asm("add.rn.f32x2 %0,%1,%2;" : "=l"(d) : "l"(a), "l"(b)); return d;
}
__device__ __forceinline__ u64 mul2(u64 a, u64 b) {
    u64 d; asm("mul.rn.f32x2 %0,%1,%2;" : "=l"(d) : "l"(a), "l"(b)); return d;
}

__device__ __forceinline__ uint32_t smem_u32(const void* p) {
    uint32_t a;
    asm("{ .reg .u64 t; cvta.to.shared.u64 t, %1; cvt.u32.u64 %0, t; }" : "=r"(a) : "l"(p));
    return a;
}

__device__ __forceinline__ void ldsm4(uint32_t r[4], uint32_t addr) {
    asm volatile("ldmatrix.sync.aligned.m8n8.x4.shared.b16 {%0,%1,%2,%3}, [%4];"
                 : "=r"(r[0]), "=r"(r[1]), "=r"(r[2]), "=r"(r[3]) : "r"(addr));
}

__device__ __forceinline__ void mma16816(float acc[4], const uint32_t a[4],
                                         uint32_t b0, uint32_t b1) {
    asm volatile(
        "mma.sync.aligned.m16n8k16.row.col.f32.bf16.bf16.f32 "
        "{%0,%1,%2,%3}, {%4,%5,%6,%7}, {%8,%9}, {%0,%1,%2,%3};"
        : "+f"(acc[0]), "+f"(acc[1]), "+f"(acc[2]), "+f"(acc[3])
        : "r"(a[0]), "r"(a[1]), "r"(a[2]), "r"(a[3]), "r"(b0), "r"(b1));
}

// ---------------------------------------------------------------------------
__global__ void zero_kernel() {
    int i = blockIdx.x * blockDim.x + threadIdx.x;
    int stride = gridDim.x * blockDim.x;
    for (int k = i; k < Nn * Ss; k += stride) g_state[0][k] = 0.f;
    for (int k = i; k < Gg * Ss; k += stride) g_gs[k] = 0.f;
}

// ---------------------------------------------------------------------------
// Per round: y = state @ W1[:32] + b1 ; stats (Sy,Qy,P) ; copy state->out.
// 8 nodes per warp iteration (halves W1 LDS traffic per node vs 4-wide).
__global__ void __launch_bounds__(192) node_gemm_kernel(
    int inb, const float* __restrict__ W1, const float* __restrict__ b1)
{
    __shared__ float sW1[32 * 128];
    __shared__ float sb1[128];
    const float* __restrict__ state_in = g_state[inb];
    float* __restrict__ state_out = g_state[inb ^ 1];

    int tid = threadIdx.x;
    for (int i = tid; i < 32 * 128; i += 192) sW1[i] = W1[i];
    if (tid < 128) sb1[tid] = b1[tid];
    __syncthreads();

    int lane = tid & 31;
    int w = tid >> 5;
    int warp_global = blockIdx.x * 6 + w;
    int nwarps = gridDim.x * 6;
    int ngroups = Nn / 8;

    float4 b1v = *(const float4*)&sb1[4 * lane];
    float4 w32v = *(const float4*)&W1[32 * 128 + 4 * lane];

    for (int g = warp_global; g < ngroups; g += nwarps) {
        int nbase = g * 8;
        float x[8];
        float4 acc[8];
#pragma unroll
        for (int e = 0; e < 8; e++) {
            x[e] = state_in[(nbase + e) * Ss + lane];
            state_out[(nbase + e) * Ss + lane] = x[e];   // fused copy
            acc[e] = b1v;
        }

#pragma unroll
        for (int i = 0; i < 32; i++) {
            float4 wv = *(const float4*)&sW1[i * 128 + 4 * lane];
#pragma unroll
            for (int e = 0; e < 8; e++) {
                float s = __shfl_sync(FULL, x[e], i);
                acc[e].x += s * wv.x; acc[e].y += s * wv.y;
                acc[e].z += s * wv.z; acc[e].w += s * wv.w;
            }
        }

#pragma unroll
        for (int e = 0; e < 8; e++)
            *(float4*)&g_y[(nbase + e) * Hh + 4 * lane] = acc[e];

#pragma unroll
        for (int e = 0; e < 8; e++) {
            float4 a = acc[e];
            float s = a.x + a.y + a.z + a.w;
            float q = a.x * a.x + a.y * a.y + a.z * a.z + a.w * a.w;
            float p = a.x * w32v.x + a.y * w32v.y + a.z * w32v.z + a.w * w32v.w;
#pragma unroll
            for (int o = 16; o; o >>= 1) {
                s += __shfl_xor_sync(FULL, s, o);
                q += __shfl_xor_sync(FULL, q, o);
                p += __shfl_xor_sync(FULL, p, o);
            }
            if (lane == 0) g_stats[nbase + e] = make_float4(s, q, p, 0.f);
        }
    }
}

// ---------------------------------------------------------------------------
// Edge kernel. B columns permuted so lane q owns output cols 8q..8q+7
// (two float4 atomics per row instead of four float2). Packed f32x2 LN2.
__global__ void __launch_bounds__(256, 2) edge_kernel(
    int inb,
    const int* __restrict__ nf, const int* __restrict__ nt,
    const float* __restrict__ ec,
    const float* __restrict__ W1,
    const float* __restrict__ g1, const float* __restrict__ be1,
    const float* __restrict__ W2, const float* __restrict__ b2,
    const float* __restrict__ g2, const float* __restrict__ be2)
{
    extern __shared__ char dsm[];
    uint32_t sbase = smem_u32(dsm);

    int tid = threadIdx.x;
    int lane = tid & 31;
    int wid = tid >> 5;

    // B staging with column permutation: MMA col n holds W2 output column
    // pi(n) = 8*q + 2*t + r  where n = 8t + 2q + r.
    for (int p = tid; p < 32 * 128; p += 256) {
        int n = p >> 7;
        int k = p & 127;
        int t = n >> 3, q0 = (n >> 1) & 3, r = n & 1;
        int pn = 8 * q0 + 2 * t + r;
        float wv = W2[k * 32 + pn];
        __nv_bfloat16 hb = __float2bfloat16(wv);
        __nv_bfloat16 lb = __float2bfloat16(wv - __bfloat162float(hb));
        *(__nv_bfloat16*)(dsm + OFF_B_H + n * APITCH + k * 2) = hb;
        *(__nv_bfloat16*)(dsm + OFF_B_L + n * APITCH + k * 2) = lb;
    }
    __syncthreads();

    float4 w32v = *(const float4*)&W1[32 * 128 + 4 * lane];
    float4 g1v  = *(const float4*)&g1[4 * lane];
    float4 be1v = *(const float4*)&be1[4 * lane];

    float Sw = w32v.x + w32v.y + w32v.z + w32v.w;
    float Qw = w32v.x * w32v.x + w32v.y * w32v.y + w32v.z * w32v.z + w32v.w * w32v.w;
#pragma unroll
    for (int o = 16; o; o >>= 1) {
        Sw += __shfl_xor_sync(FULL, Sw, o);
        Qw += __shfl_xor_sync(FULL, Qw, o);
    }

    int q = lane & 3;
    int rA = lane >> 2;
    int rB = rA + 8;

    // lane's output columns: 8q + 2t + r  (t=0..3, r=0,1) -> packed pairs
    u64 b2p[4], g2p[4], be2p[4];
#pragma unroll
    for (int t = 0; t < 4; t++) {
        int c = 8 * q + 2 * t;
        b2p[t]  = pack2(b2[c],  b2[c + 1]);
        g2p[t]  = pack2(g2[c],  g2[c + 1]);
        be2p[t] = pack2(be2[c], be2[c + 1]);
    }
    const u64 C001 = pack2(NEG_SLOPE, NEG_SLOPE);

    char* aStoreH = dsm + wid * 2 * AWARP + lane * 8;
    char* aStoreL = aStoreH + AWARP;

    int aRow = lane & 15;
    int aColB = ((lane >> 4) & 1) * 16;
    uint32_t ldAH = sbase + wid * 2 * AWARP + aRow * APITCH + aColB;
    uint32_t ldAL = ldAH + AWARP;

    int bRow = ((lane >> 4) & 1) * 8 + (lane & 7);
    int bKB = ((lane >> 3) & 1) * 16;
    uint32_t ldBH01 = sbase + OFF_B_H + bRow * APITCH + bKB;
    uint32_t ldBH23 = ldBH01 + 16 * APITCH;
    uint32_t ldBL01 = sbase + OFF_B_L + bRow * APITCH + bKB;
    uint32_t ldBL23 = ldBL01 + 16 * APITCH;

    const float4* __restrict__ yv = (const float4*)g_y;
    float* __restrict__ state_out = g_state[inb ^ 1];

    int ngroups = Ee / 16;
    int wg = blockIdx.x * 8 + wid;
    int nw = gridDim.x * 8;

    for (int g = wg; g < ngroups; g += nw) {
        int base = g * 16;

        // ---- gather + stats-based LN1 + bf16 split + stage ----
#pragma unroll
        for (int j = 0; j < 4; j++) {
            int4 NF = *(const int4*)&nf[base + 4 * j];
            float4 C = *(const float4*)&ec[base + 4 * j];
            int srcs[4] = {NF.x, NF.y, NF.z, NF.w};
            float cs[4] = {C.x, C.y, C.z, C.w};
#pragma unroll
            for (int e = 0; e < 4; e++) {
                int src = srcs[e];
                float c = cs[e];
                float4 st = g_stats[src];
                float4 a = yv[src * (Hh / 4) + lane];
                a.x = fmaf(c, w32v.x, a.x);
                a.y = fmaf(c, w32v.y, a.y);
                a.z = fmaf(c, w32v.z, a.z);
                a.w = fmaf(c, w32v.w, a.w);

                float s = fmaf(c, Sw, st.x);
                float qq = fmaf(c * c, Qw, fmaf(2.f * c, st.z, st.y));
                float mean = s * (1.f / 128.f);
                float var = qq * (1.f / 128.f) - mean * mean;
                float rstd = rsqrtf(var + LN_EPS);

                float4 hv;
                hv.x = lrelu(fmaf((a.x - mean) * rstd, g1v.x, be1v.x));
                hv.y = lrelu(fmaf((a.y - mean) * rstd, g1v.y, be1v.y));
                hv.z = lrelu(fmaf((a.z - mean) * rstd, g1v.z, be1v.z));
                hv.w = lrelu(fmaf((a.w - mean) * rstd, g1v.w, be1v.w));

                __nv_bfloat162 h01 = __float22bfloat162_rn(make_float2(hv.x, hv.y));
                __nv_bfloat162 h23 = __float22bfloat162_rn(make_float2(hv.z, hv.w));
                float2 f01 = __bfloat1622float2(h01);
                float2 f23 = __bfloat1622float2(h23);
                __nv_bfloat162 l01 = __float22bfloat162_rn(make_float2(hv.x - f01.x, hv.y - f01.y));
                __nv_bfloat162 l23 = __float22bfloat162_rn(make_float2(hv.z - f23.x, hv.w - f23.y));
                u64 packh = (u64)(*(uint32_t*)&h01) | ((u64)(*(uint32_t*)&h23) << 32);
                u64 packl = (u64)(*(uint32_t*)&l01) | ((u64)(*(uint32_t*)&l23) << 32);
                int row = 4 * j + e;
                *(u64*)(aStoreH + row * APITCH) = packh;
                *(u64*)(aStoreL + row * APITCH) = packl;
            }
        }
        __syncwarp();

        // ---- MMA: D = Ah@Bh + Ah@Bl + Al@Bh ----
        float acc[4][4];
#pragma unroll
        for (int t = 0; t < 4; t++)
#pragma unroll
            for (int j2 = 0; j2 < 4; j2++) acc[t][j2] = 0.f;

#pragma unroll
        for (int k = 0; k < 8; k++) {
            uint32_t ah[4], al[4], bh01[4], bh23[4], bl01[4], bl23[4];
            ldsm4(ah, ldAH + k * 32);
            ldsm4(al, ldAL + k * 32);
            ldsm4(bh01, ldBH01 + k * 32);
            ldsm4(bh23, ldBH23 + k * 32);
            ldsm4(bl01, ldBL01 + k * 32);
            ldsm4(bl23, ldBL23 + k * 32);

            mma16816(acc[0], ah, bh01[0], bh01[1]);
            mma16816(acc[1], ah, bh01[2], bh01[3]);
            mma16816(acc[2], ah, bh23[0], bh23[1]);
            mma16816(acc[3], ah, bh23[2], bh23[3]);

            mma16816(acc[0], ah, bl01[0], bl01[1]);
            mma16816(acc[1], ah, bl01[2], bl01[3]);
            mma16816(acc[2], ah, bl23[0], bl23[1]);
            mma16816(acc[3], ah, bl23[2], bl23[3]);

            mma16816(acc[0], al, bh01[0], bh01[1]);
            mma16816(acc[1], al, bh01[2], bh01[3]);
            mma16816(acc[2], al, bh23[0], bh23[1]);
            mma16816(acc[3], al, bh23[2], bh23[3]);
        }
        __syncwarp();

        // ---- epilogue: packed bias + LN2 (quad reduction) + float4 scatter ----
        int dstA = __ldg(&nt[base + rA]);
        int dstB = __ldg(&nt[base + rB]);

        u64 mA[4], mB[4];
#pragma unroll
        for (int t = 0; t < 4; t++) {
            mA[t] = add2(pack2(acc[t][0], acc[t][1]), b2p[t]);
            mB[t] = add2(pack2(acc[t][2], acc[t][3]), b2p[t]);
        }
        u64 sA2 = add2(add2(mA[0], mA[1]), add2(mA[2], mA[3]));
        u64 sB2 = add2(add2(mB[0], mB[1]), add2(mB[2], mB[3]));
        u64 qA2 = fma2(mA[0], mA[0], fma2(mA[1], mA[1], fma2(mA[2], mA[2], mul2(mA[3], mA[3]))));
        u64 qB2 = fma2(mB[0], mB[0], fma2(mB[1], mB[1], fma2(mB[2], mB[2], mul2(mB[3], mB[3]))));
        float t0, t1;
        unpack2(sA2, t0, t1); float sA = t0 + t1;
        unpack2(qA2, t0, t1); float qA = t0 + t1;
        unpack2(sB2, t0, t1); float sB = t0 + t1;
        unpack2(qB2, t0, t1); float qB = t0 + t1;
#pragma unroll
        for (int o = 2; o; o >>= 1) {
            sA += __shfl_xor_sync(FULL, sA, o);
            qA += __shfl_xor_sync(FULL, qA, o);
            sB += __shfl_xor_sync(FULL, sB, o);
            qB += __shfl_xor_sync(FULL, qB, o);
        }
        float meanA = sA * (1.f / 32.f);
        float rstdA = rsqrtf(qA * (1.f / 32.f) - meanA * meanA + LN_EPS);
        float meanB = sB * (1.f / 32.f);
        float rstdB = rsqrtf(qB * (1.f / 32.f) - meanB * meanB + LN_EPS);

        u64 rA2p = pack2(rstdA, rstdA), nmA2 = pack2(-meanA, -meanA);
        u64 rB2p = pack2(rstdB, rstdB), nmB2 = pack2(-meanB, -meanB);

        float vA[8], vB[8];
#pragma unroll
        for (int t = 0; t < 4; t++) {
            u64 agA = mul2(rA2p, g2p[t]);
            u64 offA = fma2(nmA2, agA, be2p[t]);
            u64 hA = fma2(mA[t], agA, offA);
            u64 pA = mul2(hA, C001);
            float h0, h1, p0, p1;
            unpack2(hA, h0, h1); unpack2(pA, p0, p1);
            vA[2 * t] = fmaxf(h0, p0); vA[2 * t + 1] = fmaxf(h1, p1);

            u64 agB = mul2(rB2p, g2p[t]);
            u64 offB = fma2(nmB2, agB, be2p[t]);
            u64 hB = fma2(mB[t], agB, offB);
            u64 pB = mul2(hB, C001);
            unpack2(hB, h0, h1); unpack2(pB, p0, p1);
            vB[2 * t] = fmaxf(h0, p0); vB[2 * t + 1] = fmaxf(h1, p1);
        }

        float* rowA = &state_out[dstA * Ss + 8 * q];
        float* rowB = &state_out[dstB * Ss + 8 * q];
        atomicAdd((float4*)&rowA[0], make_float4(vA[0], vA[1], vA[2], vA[3]));
        atomicAdd((float4*)&rowA[4], make_float4(vA[4], vA[5], vA[6], vA[7]));
        atomicAdd((float4*)&rowB[0], make_float4(vB[0], vB[1], vB[2], vB[3]));
        atomicAdd((float4*)&rowB[4], make_float4(vB[4], vB[5], vB[6], vB[7]));
    }
}

// ---------------------------------------------------------------------------
__global__ void graphsum_kernel(int inb, const int* __restrict__ ngi) {
    int t = blockIdx.x * blockDim.x + threadIdx.x;
    int total = Nn * (Ss / 4);
    if (t >= total) return;
    int n = t >> 3;
    int q = t & 7;
    const float4* s = reinterpret_cast<const float4*>(g_state[inb]);
    float4 v = s[t];
    int g = ngi[n];
    atomicAdd(reinterpret_cast<float4*>(&g_gs[g * Ss + 4 * q]), v);
}

// ---------------------------------------------------------------------------
__global__ void __launch_bounds__(128) readout_kernel(
    const float* __restrict__ Wo1, const float* __restrict__ bo1,
    const float* __restrict__ go, const float* __restrict__ beo,
    const float* __restrict__ Wo2, const float* __restrict__ bo2,
    float* __restrict__ out)
{
    __shared__ float sW[32 * 128];
    __shared__ float sb[128], sg[128], sbe[128];
    __shared__ float sW2[256];
    __shared__ float sb2[2];

    int tid = threadIdx.x;
    for (int i = tid; i < 32 * 128; i += 128) sW[i] = Wo1[i];
    sb[tid] = bo1[tid]; sg[tid] = go[tid]; sbe[tid] = beo[tid];
    sW2[tid] = Wo2[tid];
    sW2[tid + 128] = Wo2[tid + 128];
    if (tid < 2) sb2[tid] = bo2[tid];
    __syncthreads();

    int lane = tid & 31;
    int w = tid >> 5;
    int g = blockIdx.x * 4 + w;
    if (g >= Gg) return;

    float x = g_gs[g * Ss + lane];
    float4 a;
    a.x = sb[4 * lane]; a.y = sb[4 * lane + 1]; a.z = sb[4 * lane + 2]; a.w = sb[4 * lane + 3];
#pragma unroll
    for (int i = 0; i < 32; i++) {
        float xi = __shfl_sync(FULL, x, i);
        float4 wv = *(const float4*)&sW[i * 128 + 4 * lane];
        a.x += xi * wv.x; a.y += xi * wv.y; a.z += xi * wv.z; a.w += xi * wv.w;
    }
    float s = a.x + a.y + a.z + a.w;
    float s2 = a.x * a.x + a.y * a.y + a.z * a.z + a.w * a.w;
#pragma unroll
    for (int o = 16; o; o >>= 1) {
        s += __shfl_xor_sync(FULL, s, o);
        s2 += __shfl_xor_sync(FULL, s2, o);
    }
    float mean = s * (1.f / 128.f);
    float var = s2 * (1.f / 128.f) - mean * mean;
    float rstd = rsqrtf(var + LN_EPS);
    float h0 = lrelu((a.x - mean) * rstd * sg[4 * lane + 0] + sbe[4 * lane + 0]);
    float h1 = lrelu((a.y - mean) * rstd * sg[4 * lane + 1] + sbe[4 * lane + 1]);
    float h2 = lrelu((a.z - mean) * rstd * sg[4 * lane + 2] + sbe[4 * lane + 2]);
    float h3 = lrelu((a.w - mean) * rstd * sg[4 * lane + 3] + sbe[4 * lane + 3]);

    float p0 = h0 * sW2[(4 * lane + 0) * 2] + h1 * sW2[(4 * lane + 1) * 2]
             + h2 * sW2[(4 * lane + 2) * 2] + h3 * sW2[(4 * lane + 3) * 2];
    float p1 = h0 * sW2[(4 * lane + 0) * 2 + 1] + h1 * sW2[(4 * lane + 1) * 2 + 1]
             + h2 * sW2[(4 * lane + 2) * 2 + 1] + h3 * sW2[(4 * lane + 3) * 2 + 1];
#pragma unroll
    for (int o = 16; o; o >>= 1) {
        p0 += __shfl_xor_sync(FULL, p0, o);
        p1 += __shfl_xor_sync(FULL, p1, o);
    }
    if (lane == 0) {
        float mu = p0 + sb2[0];
        float v = p1 + sb2[1];
        float sp = (v > 0.f) ? v + log1pf(expf(-v)) : log1pf(expf(v));
        out[g * 2 + 0] = mu;
        out[g * 2 + 1] = sp;
    }
}

// ---------------------------------------------------------------------------
extern "C" void kernel_launch(void* const* d_in, const int* in_sizes, int n_in,
                              void* d_out, int out_size) {
    const int* nf = (const int*)d_in[0];
    const int* nt = (const int*)d_in[1];
    const float* ec = (const float*)d_in[2];
    const int* ngi = (const int*)d_in[3];
    const float* W1 = (const float*)d_in[6];
    const float* b1 = (const float*)d_in[7];
    const float* g1 = (const float*)d_in[8];
    const float* be1 = (const float*)d_in[9];
    const float* W2 = (const float*)d_in[10];
    const float* b2 = (const float*)d_in[11];
    const float* g2 = (const float*)d_in[12];
    const float* be2 = (const float*)d_in[13];
    const float* Wo1 = (const float*)d_in[14];
    const float* bo1 = (const float*)d_in[15];
    const float* go = (const float*)d_in[16];
    const float* beo = (const float*)d_in[17];
    const float* Wo2 = (const float*)d_in[18];
    const float* bo2 = (const float*)d_in[19];
    float* out = (float*)d_out;

    cudaFuncSetAttribute(edge_kernel, cudaFuncAttributeMaxDynamicSharedMemorySize, EDGE_DSMEM);

    zero_kernel<<<4096, 256>>>();

    int cur = 0;
    for (int r = 0; r < ROUNDS; r++) {
        node_gemm_kernel<<<1024, 192>>>(cur, W1, b1);   // also copies state cur -> cur^1
        edge_kernel<<<EDGE_GRID, 256, EDGE_DSMEM>>>(cur, nf, nt, ec,
                                                    W1, g1, be1, W2, b2, g2, be2);
        cur ^= 1;
    }

    graphsum_kernel<<<(Nn * 8 + 255) / 256, 256>>>(cur, ngi);
    readout_kernel<<<(Gg + 3) / 4, 128>>>(Wo1, bo1, go, beo, Wo2, bo2, out);
}